// round 3
// baseline (speedup 1.0000x reference)
#include <cuda_runtime.h>

#define EPSF 1e-5f
#define HW   16384
#define CHW  2097152   /* 128*128*128 */

// ---------------- scratch (static device memory; no allocation) ----------------
__device__ float g_xp [8*CHW];
__device__ float g_x1 [8*CHW];
__device__ float g_x2 [8*CHW];
__device__ float g_xfp[8*CHW];
__device__ float g_xrp[8*CHW];
__device__ float g_cat[8*384*HW];   // (b, 3c, h, w)

// =============================================================================
// conv1x1:  Y[b,o,p] = sum_c W[o,c] * X[b,c,p] + bias[o]
// CTA: one batch b, 128-pixel tile. 256 thr, 8x8 micro-tile (strided mapping).
// smem: Ws [c][132] (o-major rows, transposed), Xs [c][128].
// =============================================================================
__global__ __launch_bounds__(256) void conv1x1_kernel(
    const float* __restrict__ X, const float* __restrict__ Wm,
    const float* __restrict__ bias, float* __restrict__ Y)
{
    extern __shared__ float sm[];
    float* Ws = sm;              // 128*132
    float* Xs = sm + 128*132;    // 128*128
    const int tid = threadIdx.x;
    const int b   = blockIdx.y;
    const int p0  = blockIdx.x << 7;

    for (int idx = tid; idx < 128*128; idx += 256) {
        int o = idx >> 7, c = idx & 127;
        Ws[c*132 + o] = Wm[idx];
    }
    const float4* Xg = (const float4*)(X + (size_t)b*CHW + p0);
    for (int idx = tid; idx < 128*32; idx += 256) {
        int c = idx >> 5, q = idx & 31;
        float4 v = Xg[c*(HW>>2) + q];
        *((float4*)(Xs + c*128) + q) = v;
    }
    __syncthreads();

    const int tx = tid & 15, ty = tid >> 4;
    float acc[8][8];
#pragma unroll
    for (int i = 0; i < 8; i++)
#pragma unroll
        for (int j = 0; j < 8; j++) acc[i][j] = 0.f;

#pragma unroll 4
    for (int c = 0; c < 128; c++) {
        float a[8], x[8];
#pragma unroll
        for (int i = 0; i < 8; i++) a[i] = Ws[c*132 + ty + 16*i];
#pragma unroll
        for (int j = 0; j < 8; j++) x[j] = Xs[c*128 + tx + 16*j];
#pragma unroll
        for (int i = 0; i < 8; i++)
#pragma unroll
            for (int j = 0; j < 8; j++) acc[i][j] = fmaf(a[i], x[j], acc[i][j]);
    }

#pragma unroll
    for (int i = 0; i < 8; i++) {
        int o = ty + 16*i;
        float bo = bias[o];
        float* Yp = Y + (size_t)b*CHW + (size_t)o*HW + p0 + tx;
#pragma unroll
        for (int j = 0; j < 8; j++) Yp[16*j] = acc[i][j] + bo;
    }
}

// =============================================================================
// block reduction: sum + sumsq over 256 threads
// =============================================================================
__device__ __forceinline__ void block_reduce_2(float& s, float& q, float* red)
{
#pragma unroll
    for (int off = 16; off > 0; off >>= 1) {
        s += __shfl_down_sync(0xffffffffu, s, off);
        q += __shfl_down_sync(0xffffffffu, q, off);
    }
    const int wid = threadIdx.x >> 5;
    if ((threadIdx.x & 31) == 0) { red[wid] = s; red[8 + wid] = q; }
    __syncthreads();
    s = 0.f; q = 0.f;
#pragma unroll
    for (int i = 0; i < 8; i++) { s += red[i]; q += red[8 + i]; }
    __syncthreads();
}

// =============================================================================
// Attention: one CTA per (h, b, branch).
//   S[c][d]  = sum_w P[b,c,h,w]*Qp[b,d,h,w]   (P=x1|x2, Qp=xfp|xrp)
//   S <- inorm(S);  F[c][w] = sum_d S[c][d]*xp[b,d,h,w];  F <- inorm(F)
//   cat[b, br*128 + c, h, w] = F[c][w]
// =============================================================================
__global__ __launch_bounds__(256) void attn_kernel()
{
    extern __shared__ float sm[];
    float* bufA = sm;               // [128][129]
    float* bufB = sm + 128*129;     // [128][129]
    __shared__ float red[16];

    const int h = blockIdx.x, b = blockIdx.y, br = blockIdx.z;
    const float* P = br ? g_x2  : g_x1;
    const float* Q = br ? g_xrp : g_xfp;
    const int tid = threadIdx.x, tx = tid & 15, ty = tid >> 4;
    const size_t base = (size_t)b*CHW + (size_t)h*128;

    for (int idx = tid; idx < 128*32; idx += 256) {
        int r = idx >> 5, q = idx & 31;
        float4 v = *(const float4*)(P + base + (size_t)r*HW + 4*q);
        float* d0 = bufA + r*129 + 4*q;
        d0[0]=v.x; d0[1]=v.y; d0[2]=v.z; d0[3]=v.w;
        float4 u = *(const float4*)(Q + base + (size_t)r*HW + 4*q);
        float* e0 = bufB + r*129 + 4*q;
        e0[0]=u.x; e0[1]=u.y; e0[2]=u.z; e0[3]=u.w;
    }
    __syncthreads();

    // GEMM1: S = P * Q^T   (thread tile c = ty+16i, d = tx+16j)
    float s[8][8];
#pragma unroll
    for (int i=0;i<8;i++)
#pragma unroll
        for (int j=0;j<8;j++) s[i][j]=0.f;
#pragma unroll 4
    for (int w = 0; w < 128; w++) {
        float a[8], bb[8];
#pragma unroll
        for (int i=0;i<8;i++) a[i]  = bufA[(ty+16*i)*129 + w];
#pragma unroll
        for (int j=0;j<8;j++) bb[j] = bufB[(tx+16*j)*129 + w];
#pragma unroll
        for (int i=0;i<8;i++)
#pragma unroll
            for (int j=0;j<8;j++) s[i][j] = fmaf(a[i], bb[j], s[i][j]);
    }

    // instance norm of S over all 16384 values
    float ls = 0.f, lq = 0.f;
#pragma unroll
    for (int i=0;i<8;i++)
#pragma unroll
        for (int j=0;j<8;j++) { ls += s[i][j]; lq += s[i][j]*s[i][j]; }
    block_reduce_2(ls, lq, red);
    float mean = ls * (1.f/16384.f);
    float var  = lq * (1.f/16384.f) - mean*mean;
    float inv  = rsqrtf(var + EPSF);

    // restage: bufA <- S^T (Sd[d][c]), bufB <- xp tile   (reduce's sync covers hazards)
#pragma unroll
    for (int i=0;i<8;i++)
#pragma unroll
        for (int j=0;j<8;j++)
            bufA[(tx+16*j)*129 + (ty+16*i)] = (s[i][j]-mean)*inv;
    for (int idx = tid; idx < 128*32; idx += 256) {
        int r = idx >> 5, q = idx & 31;
        float4 v = *(const float4*)(g_xp + base + (size_t)r*HW + 4*q);
        float* e0 = bufB + r*129 + 4*q;
        e0[0]=v.x; e0[1]=v.y; e0[2]=v.z; e0[3]=v.w;
    }
    __syncthreads();

    // GEMM2: F[c][w] = sum_d Sd[d][c] * Xp[d][w]
    float f[8][8];
#pragma unroll
    for (int i=0;i<8;i++)
#pragma unroll
        for (int j=0;j<8;j++) f[i][j]=0.f;
#pragma unroll 4
    for (int d = 0; d < 128; d++) {
        float a[8], bb[8];
#pragma unroll
        for (int i=0;i<8;i++) a[i]  = bufA[d*129 + ty + 16*i];
#pragma unroll
        for (int j=0;j<8;j++) bb[j] = bufB[d*129 + tx + 16*j];
#pragma unroll
        for (int i=0;i<8;i++)
#pragma unroll
            for (int j=0;j<8;j++) f[i][j] = fmaf(a[i], bb[j], f[i][j]);
    }

    // instance norm of F
    ls = 0.f; lq = 0.f;
#pragma unroll
    for (int i=0;i<8;i++)
#pragma unroll
        for (int j=0;j<8;j++) { ls += f[i][j]; lq += f[i][j]*f[i][j]; }
    block_reduce_2(ls, lq, red);
    mean = ls * (1.f/16384.f);
    var  = lq * (1.f/16384.f) - mean*mean;
    inv  = rsqrtf(var + EPSF);

    const int co = br << 7;
#pragma unroll
    for (int i=0;i<8;i++) {
        int c = ty + 16*i;
        float* dst = g_cat + ((size_t)b*384 + co + c)*HW + (size_t)h*128 + tx;
#pragma unroll
        for (int j=0;j<8;j++) dst[16*j] = (f[i][j]-mean)*inv;
    }
}

// =============================================================================
// copy x into cat channels 256..383 (contiguous per batch)
// =============================================================================
__global__ void copy_x_kernel(const float* __restrict__ x)
{
    int idx = blockIdx.x*256 + threadIdx.x;           // over 4194304 float4
    int b = idx >> 19;                                 // CHW/4 = 524288
    int r = idx & 524287;
    ((float4*)g_cat)[((size_t)b*384 + 256)*(HW>>2) + r] = ((const float4*)x)[idx];
}

// =============================================================================
// conv3x3 (pad 1) + BN(eval) + ReLU, implicit GEMM.
// CTA: one (b, h) row x 128 o-channels. K loop: ci chunks of 8 x 9 taps.
// smem: Wc [72][132] ([k][o] transposed), Is [8*3][132] input rows with halo.
// =============================================================================
__global__ __launch_bounds__(256) void conv3x3_kernel(
    const float* __restrict__ Wm, const float* __restrict__ bm,
    const float* __restrict__ gamma, const float* __restrict__ beta,
    const float* __restrict__ rmean, const float* __restrict__ rvar,
    float* __restrict__ out)
{
    extern __shared__ float sm[];
    float* Wc = sm;            // 72*132
    float* Is = sm + 72*132;   // 24*132
    const int h  = blockIdx.x;
    const int o0 = blockIdx.y << 7;
    const int b  = blockIdx.z;
    const int tid = threadIdx.x, tx = tid & 15, ty = tid >> 4;

    float acc[8][8];
#pragma unroll
    for (int i=0;i<8;i++)
#pragma unroll
        for (int j=0;j<8;j++) acc[i][j]=0.f;

    const float* catb = g_cat + (size_t)b*384*HW;

    for (int ci0 = 0; ci0 < 384; ci0 += 8) {
        __syncthreads();
        for (int idx = tid; idx < 9216; idx += 256) {        // 128 o x 72 k
            int ol = idx / 72, r = idx - ol*72;
            Wc[r*132 + ol] = Wm[(size_t)(o0+ol)*3456 + ci0*9 + r];
        }
        for (int idx = tid; idx < 8*3*132; idx += 256) {     // input + halo
            int ci = idx / 396, rr = idx - ci*396;
            int row = rr / 132, col = rr - row*132;
            int hh = h + row - 1, w = col - 1;
            float v = 0.f;
            if (((unsigned)hh < 128u) && ((unsigned)w < 128u))
                v = catb[(size_t)(ci0+ci)*HW + hh*128 + w];
            Is[(ci*3+row)*132 + col] = v;
        }
        __syncthreads();

        for (int ci = 0; ci < 8; ci++) {
#pragma unroll
            for (int t = 0; t < 9; t++) {
                const int kh = t/3, kw = t - kh*3;
                float wv[8], iv[8];
#pragma unroll
                for (int i=0;i<8;i++) wv[i] = Wc[(ci*9+t)*132 + ty + 16*i];
#pragma unroll
                for (int j=0;j<8;j++) iv[j] = Is[(ci*3+kh)*132 + tx + 16*j + kw];
#pragma unroll
                for (int i=0;i<8;i++)
#pragma unroll
                    for (int j=0;j<8;j++) acc[i][j] = fmaf(wv[i], iv[j], acc[i][j]);
            }
        }
    }

#pragma unroll
    for (int i=0;i<8;i++) {
        int o = o0 + ty + 16*i;
        float sc = gamma[o] * rsqrtf(rvar[o] + EPSF);
        float sh = beta[o] + (bm[o] - rmean[o]) * sc;
        float* dst = out + ((size_t)b*384 + o)*HW + (size_t)h*128 + tx;
#pragma unroll
        for (int j=0;j<8;j++) {
            float y = fmaf(acc[i][j], sc, sh);
            dst[16*j] = fmaxf(y, 0.f);
        }
    }
}

// =============================================================================
extern "C" void kernel_launch(void* const* d_in, const int* in_sizes, int n_in,
                              void* d_out, int out_size)
{
    const float* x  = (const float*)d_in[0];
    const float* xf = (const float*)d_in[1];
    const float* xr = (const float*)d_in[2];
    const float* Wx = (const float*)d_in[3];
    const float* bx = (const float*)d_in[4];
    const float* W1 = (const float*)d_in[5];
    const float* b1 = (const float*)d_in[6];
    const float* W2 = (const float*)d_in[7];
    const float* b2 = (const float*)d_in[8];
    const float* Wf = (const float*)d_in[9];
    const float* bf = (const float*)d_in[10];
    const float* Wr = (const float*)d_in[11];
    const float* br = (const float*)d_in[12];
    const float* Wm = (const float*)d_in[13];
    const float* bm = (const float*)d_in[14];
    const float* gamma = (const float*)d_in[15];
    const float* beta  = (const float*)d_in[16];
    const float* rmean = (const float*)d_in[17];
    const float* rvar  = (const float*)d_in[18];
    float* out = (float*)d_out;

    void *pxp, *px1, *px2, *pxfp, *pxrp;
    cudaGetSymbolAddress(&pxp,  g_xp);
    cudaGetSymbolAddress(&px1,  g_x1);
    cudaGetSymbolAddress(&px2,  g_x2);
    cudaGetSymbolAddress(&pxfp, g_xfp);
    cudaGetSymbolAddress(&pxrp, g_xrp);

    cudaFuncSetAttribute(conv1x1_kernel, cudaFuncAttributeMaxDynamicSharedMemorySize, 133120);
    cudaFuncSetAttribute(attn_kernel,    cudaFuncAttributeMaxDynamicSharedMemorySize, 132096);
    cudaFuncSetAttribute(conv3x3_kernel, cudaFuncAttributeMaxDynamicSharedMemorySize, 50688);

    dim3 g1(128, 8);
    conv1x1_kernel<<<g1, 256, 133120>>>(x,  Wx, bx, (float*)pxp);
    conv1x1_kernel<<<g1, 256, 133120>>>((const float*)pxp, W1, b1, (float*)px1);
    conv1x1_kernel<<<g1, 256, 133120>>>((const float*)pxp, W2, b2, (float*)px2);
    conv1x1_kernel<<<g1, 256, 133120>>>(xf, Wf, bf, (float*)pxfp);
    conv1x1_kernel<<<g1, 256, 133120>>>(xr, Wr, br, (float*)pxrp);
    copy_x_kernel<<<16384, 256>>>(x);
    attn_kernel<<<dim3(128, 8, 2), 256, 132096>>>();
    conv3x3_kernel<<<dim3(128, 3, 8), 256, 50688>>>(Wm, bm, gamma, beta, rmean, rvar, out);
}

// round 5
// speedup vs baseline: 2.6716x; 2.6716x over previous
#include <cuda_runtime.h>
#include <cuda_bf16.h>
#include <cstdint>

#define EPSF 1e-5f
#define HW   16384
#define CHW  2097152

// ---------------- scratch (static device memory; zero-initialized) ----------
__device__ float g_xp [8*CHW];
__device__ float g_x1 [8*CHW];
__device__ float g_x2 [8*CHW];
__device__ float g_xfp[8*CHW];
__device__ float g_xrp[8*CHW];
__device__ float g_cat[8*256*HW];                    // (b, 2c, h, w) attn outputs
__device__ unsigned short g_wh[9*6*384*64];          // W hi: [tap][chunk][o][ci]
__device__ unsigned short g_wl[9*6*384*64];          // W lo
__device__ unsigned short g_bhi[8ull*130*130*384];   // input hi: [b][hp][wp][ci]
__device__ unsigned short g_blo[8ull*130*130*384];   // input lo (halo rows stay 0)

// ---------------- helpers ----------------
__device__ __forceinline__ uint32_t smem_u32(const void* p){
    uint32_t a; asm("{ .reg .u64 t; cvta.to.shared.u64 t, %1; cvt.u32.u64 %0, t; }"
                    : "=r"(a) : "l"(p)); return a;
}
#define SWZ(x) ((x) ^ (((x)>>3)&0x70))
#define CP16(dst, src) asm volatile("cp.async.cg.shared.global [%0], [%1], 16;" \
    :: "r"((uint32_t)(dst)), "l"((const void*)(src)) : "memory")
#define CP_COMMIT() asm volatile("cp.async.commit_group;" ::: "memory")
#define CP_WAIT0()  asm volatile("cp.async.wait_group 0;" ::: "memory")
#define LDSM4(r0,r1,r2,r3,a) asm volatile( \
    "ldmatrix.sync.aligned.m8n8.x4.shared.b16 {%0,%1,%2,%3}, [%4];" \
    : "=r"(r0),"=r"(r1),"=r"(r2),"=r"(r3) : "r"(a))
#define MMA16816(c,a,b) asm volatile( \
    "mma.sync.aligned.m16n8k16.row.col.f32.bf16.bf16.f32 " \
    "{%0,%1,%2,%3},{%4,%5,%6,%7},{%8,%9},{%0,%1,%2,%3};" \
    : "+f"((c)[0]),"+f"((c)[1]),"+f"((c)[2]),"+f"((c)[3]) \
    : "r"((a)[0]),"r"((a)[1]),"r"((a)[2]),"r"((a)[3]), "r"((b)[0]),"r"((b)[1]))

// ============================ conv1x1 (fp32) ================================
__global__ __launch_bounds__(256) void conv1x1_kernel(
    const float* __restrict__ X, const float* __restrict__ Wm,
    const float* __restrict__ bias, float* __restrict__ Y)
{
    extern __shared__ float sm[];
    float* Ws = sm; float* Xs = sm + 128*132;
    const int tid = threadIdx.x, b = blockIdx.y, p0 = blockIdx.x << 7;
    for (int idx = tid; idx < 128*128; idx += 256){
        int o = idx >> 7, c = idx & 127; Ws[c*132 + o] = Wm[idx];
    }
    const float4* Xg = (const float4*)(X + (size_t)b*CHW + p0);
    for (int idx = tid; idx < 128*32; idx += 256){
        int c = idx >> 5, q = idx & 31;
        *((float4*)(Xs + c*128) + q) = Xg[c*(HW>>2) + q];
    }
    __syncthreads();
    const int tx = tid & 15, ty = tid >> 4;
    float acc[8][8];
#pragma unroll
    for (int i=0;i<8;i++)
#pragma unroll
        for (int j=0;j<8;j++) acc[i][j]=0.f;
#pragma unroll 4
    for (int c = 0; c < 128; c++){
        float a[8], x[8];
#pragma unroll
        for (int i=0;i<8;i++) a[i] = Ws[c*132 + ty + 16*i];
#pragma unroll
        for (int j=0;j<8;j++) x[j] = Xs[c*128 + tx + 16*j];
#pragma unroll
        for (int i=0;i<8;i++)
#pragma unroll
            for (int j=0;j<8;j++) acc[i][j] = fmaf(a[i], x[j], acc[i][j]);
    }
#pragma unroll
    for (int i=0;i<8;i++){
        int o = ty + 16*i; float bo = bias[o];
        float* Yp = Y + (size_t)b*CHW + (size_t)o*HW + p0 + tx;
#pragma unroll
        for (int j=0;j<8;j++) Yp[16*j] = acc[i][j] + bo;
    }
}

// ============================ attention (fp32) ==============================
__device__ __forceinline__ void block_reduce_2(float& s, float& q, float* red)
{
#pragma unroll
    for (int off=16; off>0; off>>=1){
        s += __shfl_down_sync(0xffffffffu, s, off);
        q += __shfl_down_sync(0xffffffffu, q, off);
    }
    const int wid = threadIdx.x >> 5;
    if ((threadIdx.x & 31) == 0){ red[wid] = s; red[8+wid] = q; }
    __syncthreads();
    s = 0.f; q = 0.f;
#pragma unroll
    for (int i=0;i<8;i++){ s += red[i]; q += red[8+i]; }
    __syncthreads();
}

__global__ __launch_bounds__(256) void attn_kernel()
{
    extern __shared__ float sm[];
    float* bufA = sm; float* bufB = sm + 128*129;
    __shared__ float red[16];
    const int h = blockIdx.x, b = blockIdx.y, br = blockIdx.z;
    const float* P = br ? g_x2  : g_x1;
    const float* Q = br ? g_xrp : g_xfp;
    const int tid = threadIdx.x, tx = tid & 15, ty = tid >> 4;
    const size_t base = (size_t)b*CHW + (size_t)h*128;

    for (int idx = tid; idx < 128*32; idx += 256){
        int r = idx >> 5, q = idx & 31;
        float4 v = *(const float4*)(P + base + (size_t)r*HW + 4*q);
        float* d0 = bufA + r*129 + 4*q; d0[0]=v.x; d0[1]=v.y; d0[2]=v.z; d0[3]=v.w;
        float4 u = *(const float4*)(Q + base + (size_t)r*HW + 4*q);
        float* e0 = bufB + r*129 + 4*q; e0[0]=u.x; e0[1]=u.y; e0[2]=u.z; e0[3]=u.w;
    }
    __syncthreads();

    float s[8][8];
#pragma unroll
    for (int i=0;i<8;i++)
#pragma unroll
        for (int j=0;j<8;j++) s[i][j]=0.f;
#pragma unroll 4
    for (int w = 0; w < 128; w++){
        float a[8], bb[8];
#pragma unroll
        for (int i=0;i<8;i++) a[i]  = bufA[(ty+16*i)*129 + w];
#pragma unroll
        for (int j=0;j<8;j++) bb[j] = bufB[(tx+16*j)*129 + w];
#pragma unroll
        for (int i=0;i<8;i++)
#pragma unroll
            for (int j=0;j<8;j++) s[i][j] = fmaf(a[i], bb[j], s[i][j]);
    }
    float ls=0.f, lq=0.f;
#pragma unroll
    for (int i=0;i<8;i++)
#pragma unroll
        for (int j=0;j<8;j++){ ls += s[i][j]; lq += s[i][j]*s[i][j]; }
    block_reduce_2(ls, lq, red);
    float mean = ls*(1.f/16384.f);
    float inv  = rsqrtf(lq*(1.f/16384.f) - mean*mean + EPSF);

#pragma unroll
    for (int i=0;i<8;i++)
#pragma unroll
        for (int j=0;j<8;j++)
            bufA[(tx+16*j)*129 + (ty+16*i)] = (s[i][j]-mean)*inv;
    for (int idx = tid; idx < 128*32; idx += 256){
        int r = idx >> 5, q = idx & 31;
        float4 v = *(const float4*)(g_xp + base + (size_t)r*HW + 4*q);
        float* e0 = bufB + r*129 + 4*q; e0[0]=v.x; e0[1]=v.y; e0[2]=v.z; e0[3]=v.w;
    }
    __syncthreads();

    float f[8][8];
#pragma unroll
    for (int i=0;i<8;i++)
#pragma unroll
        for (int j=0;j<8;j++) f[i][j]=0.f;
#pragma unroll 4
    for (int d = 0; d < 128; d++){
        float a[8], bb[8];
#pragma unroll
        for (int i=0;i<8;i++) a[i]  = bufA[d*129 + ty + 16*i];
#pragma unroll
        for (int j=0;j<8;j++) bb[j] = bufB[d*129 + tx + 16*j];
#pragma unroll
        for (int i=0;i<8;i++)
#pragma unroll
            for (int j=0;j<8;j++) f[i][j] = fmaf(a[i], bb[j], f[i][j]);
    }
    ls=0.f; lq=0.f;
#pragma unroll
    for (int i=0;i<8;i++)
#pragma unroll
        for (int j=0;j<8;j++){ ls += f[i][j]; lq += f[i][j]*f[i][j]; }
    block_reduce_2(ls, lq, red);
    mean = ls*(1.f/16384.f);
    inv  = rsqrtf(lq*(1.f/16384.f) - mean*mean + EPSF);

    const int co = br << 7;
#pragma unroll
    for (int i=0;i<8;i++){
        int c = ty + 16*i;
        float* dst = g_cat + ((size_t)b*256 + co + c)*HW + (size_t)h*128 + tx;
#pragma unroll
        for (int j=0;j<8;j++) dst[16*j] = (f[i][j]-mean)*inv;
    }
}

// ============ weight pre-split: [o][ci][3][3] -> [tap][chunk][o][ci] hi/lo ===
__global__ void presplit_kernel(const float* __restrict__ Wm)
{
    int idx = blockIdx.x*256 + threadIdx.x;      // 9*6*384*64 = 1327104
    if (idx >= 9*6*384*64) return;
    int ci = idx & 63;
    int o  = (idx >> 6) % 384;
    int r  = idx >> 6; r /= 384;
    int chunk = r % 6, tap = r / 6;
    float v = Wm[(size_t)o*3456 + (chunk*64 + ci)*9 + tap];
    __nv_bfloat16 h = __float2bfloat16(v);
    float hf = __bfloat162float(h);
    __nv_bfloat16 l = __float2bfloat16(v - hf);
    g_wh[idx] = __bfloat16_as_ushort(h);
    g_wl[idx] = __bfloat16_as_ushort(l);
}

// ===== input to channels-last bf16 hi/lo: [b][hp][wp][ci], interior only ====
__global__ __launch_bounds__(256) void padcvt_kernel(const float* __restrict__ x)
{
    __shared__ float tile[64*129];
    const int c0 = blockIdx.x << 6, h = blockIdx.y, b = blockIdx.z;
    const int tid = threadIdx.x;
    for (int idx = tid; idx < 64*128; idx += 256){
        int ci = idx >> 7, w = idx & 127;
        int cg = c0 + ci;
        float v = (cg < 256)
            ? g_cat[((size_t)b*256 + cg)*HW + h*128 + w]
            : x[((size_t)b*128 + (cg-256))*HW + h*128 + w];
        tile[ci*129 + w] = v;
    }
    __syncthreads();
    const size_t obase = (((size_t)b*130 + (h+1))*130)*384;   // elements, wp=0
    for (int idx = tid; idx < 128*8; idx += 256){
        int w = idx >> 3, u = idx & 7;
        unsigned Hp[4], Lp[4];
#pragma unroll
        for (int e2 = 0; e2 < 4; e2++){
            float v0 = tile[(u*8 + 2*e2    )*129 + w];
            float v1 = tile[(u*8 + 2*e2 + 1)*129 + w];
            unsigned hp, lp;
            asm("cvt.rn.bf16x2.f32 %0, %1, %2;" : "=r"(hp) : "f"(v1), "f"(v0));
            float h0 = __uint_as_float(hp << 16);
            float h1 = __uint_as_float(hp & 0xffff0000u);
            asm("cvt.rn.bf16x2.f32 %0, %1, %2;" : "=r"(lp) : "f"(v1-h1), "f"(v0-h0));
            Hp[e2] = hp; Lp[e2] = lp;
        }
        size_t off2 = (obase + (size_t)(w+1)*384 + c0 + u*8) * 2;   // bytes
        *(uint4*)((char*)g_bhi + off2) = make_uint4(Hp[0],Hp[1],Hp[2],Hp[3]);
        *(uint4*)((char*)g_blo + off2) = make_uint4(Lp[0],Lp[1],Lp[2],Lp[3]);
    }
}

// =================== conv3x3 via mma.sync bf16 (hi/lo) ======================
// CTA (h, ob, b): M=128 o, N=128 w. 54 iters = 9 taps x 6 ci-chunks(64).
// Stage: Ah|Al 16KB each ([o][ci] k-major), Bh|Bl 16.6KB ([wp 130][ci]).
#define OFF_AH 0
#define OFF_AL 16384
#define OFF_BH 32768
#define OFF_BL 50176
#define STAGE  67584

__global__ __launch_bounds__(256) void conv3x3_tc(
    const float* __restrict__ bm, const float* __restrict__ gamma,
    const float* __restrict__ beta, const float* __restrict__ rmean,
    const float* __restrict__ rvar, float* __restrict__ out)
{
    extern __shared__ char dsm[];
    const int tid = threadIdx.x, l = tid & 31, wid = tid >> 5;
    const int mw = wid & 1, nw = wid >> 1;        // warp grid 2(M) x 4(N)
    const int h = blockIdx.x, o0 = blockIdx.y << 7, b = blockIdx.z;
    const uint32_t sb = smem_u32(dsm);

    float acc[4][4][4];
#pragma unroll
    for (int f=0;f<4;f++)
#pragma unroll
        for (int g=0;g<4;g++)
#pragma unroll
            for (int e=0;e<4;e++) acc[f][g][e] = 0.f;

    auto stage = [&](int it, int st){
        int tap = it/6, chunk = it - tap*6;
        int kh = tap/3;
        uint32_t s0 = sb + st*STAGE;
        const char* srcAh = (const char*)g_wh + (((size_t)tap*6 + chunk)*384 + o0)*128;
        const char* srcAl = (const char*)g_wl + (((size_t)tap*6 + chunk)*384 + o0)*128;
        for (int u = tid; u < 1024; u += 256){
            uint32_t d = SWZ(u*16);
            CP16(s0 + OFF_AH + d, srcAh + u*16);
            CP16(s0 + OFF_AL + d, srcAl + u*16);
        }
        size_t rowbase = ((size_t)b*130 + (h+kh))*130*768 + (size_t)chunk*128;
        const char* BH = (const char*)g_bhi;
        const char* BL = (const char*)g_blo;
        for (int u = tid; u < 1040; u += 256){
            int wp = u >> 3, j = u & 7;
            size_t so = rowbase + (size_t)wp*768 + j*16;
            uint32_t d = SWZ(wp*128 + j*16);
            CP16(s0 + OFF_BH + d, BH + so);
            CP16(s0 + OFF_BL + d, BL + so);
        }
    };

    stage(0, 0); CP_COMMIT(); CP_WAIT0(); __syncthreads();

    for (int it = 0; it < 54; it++){
        const int p = it & 1;
        if (it + 1 < 54){ stage(it+1, 1-p); CP_COMMIT(); }

        const int kw = (it/6) % 3;
        const uint32_t s0 = sb + p*STAGE;
#pragma unroll
        for (int ks = 0; ks < 4; ks++){
            uint32_t ah[4][4], al[4][4], bh[4][2], bl[4][2];
            const uint32_t abyte = ks*32 + ((l>>4)<<4);
#pragma unroll
            for (int f = 0; f < 4; f++){
                int row = mw*64 + f*16 + (l & 15);
                uint32_t off = SWZ((uint32_t)(row*128) + abyte);
                LDSM4(ah[f][0],ah[f][1],ah[f][2],ah[f][3], s0 + OFF_AH + off);
                LDSM4(al[f][0],al[f][1],al[f][2],al[f][3], s0 + OFF_AL + off);
            }
            const uint32_t bbyte = ks*32 + (((l>>3)&1)<<4);
#pragma unroll
            for (int g2 = 0; g2 < 2; g2++){
                int rowb = nw*32 + g2*16 + kw + (l & 7) + ((l>>4)<<3);
                uint32_t off = SWZ((uint32_t)(rowb*128) + bbyte);
                uint32_t t0,t1,t2,t3;
                LDSM4(t0,t1,t2,t3, s0 + OFF_BH + off);
                bh[g2*2][0]=t0; bh[g2*2][1]=t1; bh[g2*2+1][0]=t2; bh[g2*2+1][1]=t3;
                LDSM4(t0,t1,t2,t3, s0 + OFF_BL + off);
                bl[g2*2][0]=t0; bl[g2*2][1]=t1; bl[g2*2+1][0]=t2; bl[g2*2+1][1]=t3;
            }
#pragma unroll
            for (int f = 0; f < 4; f++)
#pragma unroll
                for (int g = 0; g < 4; g++){
                    MMA16816(acc[f][g], ah[f], bh[g]);
                    MMA16816(acc[f][g], ah[f], bl[g]);
                    MMA16816(acc[f][g], al[f], bh[g]);
                }
        }
        CP_WAIT0();
        __syncthreads();
    }

    // epilogue: BN + ReLU, float2 stores
#pragma unroll
    for (int f = 0; f < 4; f++){
        int o1 = o0 + mw*64 + f*16 + (l >> 2);
        int o2 = o1 + 8;
        float sc1 = gamma[o1] * rsqrtf(rvar[o1] + EPSF);
        float sh1 = beta[o1] + (bm[o1] - rmean[o1]) * sc1;
        float sc2 = gamma[o2] * rsqrtf(rvar[o2] + EPSF);
        float sh2 = beta[o2] + (bm[o2] - rmean[o2]) * sc2;
        float* r1 = out + ((size_t)(b*384 + o1))*HW + (size_t)h*128;
        float* r2 = out + ((size_t)(b*384 + o2))*HW + (size_t)h*128;
#pragma unroll
        for (int g = 0; g < 4; g++){
            int w = nw*32 + g*8 + 2*(l & 3);
            float2 v1, v2;
            v1.x = fmaxf(fmaf(acc[f][g][0], sc1, sh1), 0.f);
            v1.y = fmaxf(fmaf(acc[f][g][1], sc1, sh1), 0.f);
            v2.x = fmaxf(fmaf(acc[f][g][2], sc2, sh2), 0.f);
            v2.y = fmaxf(fmaf(acc[f][g][3], sc2, sh2), 0.f);
            *(float2*)(r1 + w) = v1;
            *(float2*)(r2 + w) = v2;
        }
    }
}

// =============================================================================
extern "C" void kernel_launch(void* const* d_in, const int* in_sizes, int n_in,
                              void* d_out, int out_size)
{
    const float* x  = (const float*)d_in[0];
    const float* xf = (const float*)d_in[1];
    const float* xr = (const float*)d_in[2];
    const float* Wx = (const float*)d_in[3];
    const float* bx = (const float*)d_in[4];
    const float* W1 = (const float*)d_in[5];
    const float* b1 = (const float*)d_in[6];
    const float* W2 = (const float*)d_in[7];
    const float* b2 = (const float*)d_in[8];
    const float* Wf = (const float*)d_in[9];
    const float* bf = (const float*)d_in[10];
    const float* Wr = (const float*)d_in[11];
    const float* br = (const float*)d_in[12];
    const float* Wm = (const float*)d_in[13];
    const float* bm = (const float*)d_in[14];
    const float* gamma = (const float*)d_in[15];
    const float* beta  = (const float*)d_in[16];
    const float* rmean = (const float*)d_in[17];
    const float* rvar  = (const float*)d_in[18];
    float* out = (float*)d_out;

    void *pxp, *px1, *px2, *pxfp, *pxrp;
    cudaGetSymbolAddress(&pxp,  g_xp);
    cudaGetSymbolAddress(&px1,  g_x1);
    cudaGetSymbolAddress(&px2,  g_x2);
    cudaGetSymbolAddress(&pxfp, g_xfp);
    cudaGetSymbolAddress(&pxrp, g_xrp);

    cudaFuncSetAttribute(conv1x1_kernel, cudaFuncAttributeMaxDynamicSharedMemorySize, 133120);
    cudaFuncSetAttribute(attn_kernel,    cudaFuncAttributeMaxDynamicSharedMemorySize, 132096);
    cudaFuncSetAttribute(conv3x3_tc,     cudaFuncAttributeMaxDynamicSharedMemorySize, 2*STAGE);

    dim3 g1(128, 8);
    conv1x1_kernel<<<g1, 256, 133120>>>(x,  Wx, bx, (float*)pxp);
    conv1x1_kernel<<<g1, 256, 133120>>>((const float*)pxp, W1, b1, (float*)px1);
    conv1x1_kernel<<<g1, 256, 133120>>>((const float*)pxp, W2, b2, (float*)px2);
    conv1x1_kernel<<<g1, 256, 133120>>>(xf, Wf, bf, (float*)pxfp);
    conv1x1_kernel<<<g1, 256, 133120>>>(xr, Wr, br, (float*)pxrp);
    attn_kernel<<<dim3(128, 8, 2), 256, 132096>>>();
    presplit_kernel<<<5184, 256>>>(Wm);
    padcvt_kernel<<<dim3(6, 128, 8), 256>>>(x);
    conv3x3_tc<<<dim3(128, 3, 8), 256, 2*STAGE>>>(bm, gamma, beta, rmean, rvar, out);
}

// round 6
// speedup vs baseline: 3.3848x; 1.2669x over previous
#include <cuda_runtime.h>
#include <cuda_bf16.h>
#include <cstdint>

#define EPSF 1e-5f
#define HW   16384
#define CHW  2097152

// ---------------- scratch (static device memory) ----------------
__device__ float g_cat[8*256*HW];                       // attn outputs fp32 (b,2c,h,w)
__device__ float g_wcf[5*16384];                        // composed 1x1 weights fp32
__device__ float g_bcf[5*128];                          // composed biases
__device__ __align__(16) unsigned short g_wsh[5*2*128*64];  // [which][pn][o][ci64] hi
__device__ __align__(16) unsigned short g_wsl[5*2*128*64];
__device__ __align__(16) unsigned short g_tih[3ull*8*CHW];  // inputs T: [inp][b][h][w][c] hi
__device__ __align__(16) unsigned short g_til[3ull*8*CHW];
__device__ __align__(16) unsigned short g_x1h[8*CHW], g_x1l[8*CHW];  // [b][h][c][w]
__device__ __align__(16) unsigned short g_x2h[8*CHW], g_x2l[8*CHW];
__device__ __align__(16) unsigned short g_xfh[8*CHW], g_xfl[8*CHW];
__device__ __align__(16) unsigned short g_xrh[8*CHW], g_xrl[8*CHW];
__device__ __align__(16) unsigned short g_xph[8*CHW], g_xpl[8*CHW];  // [b][h][w][d]
__device__ unsigned short g_wh[9*6*384*64];             // conv3x3 W hi: [tap][chunk][o][ci]
__device__ unsigned short g_wl[9*6*384*64];
__device__ unsigned short g_bhi[8ull*130*130*384];      // conv3x3 in hi: [b][hp][wp][ci]
__device__ unsigned short g_blo[8ull*130*130*384];

// ---------------- helpers ----------------
__device__ __forceinline__ uint32_t smem_u32(const void* p){
    uint32_t a; asm("{ .reg .u64 t; cvta.to.shared.u64 t, %1; cvt.u32.u64 %0, t; }"
                    : "=r"(a) : "l"(p)); return a;
}
#define SWZ(x) ((x) ^ (((x)>>3)&0x70))
#define CP16(dst, src) asm volatile("cp.async.cg.shared.global [%0], [%1], 16;" \
    :: "r"((uint32_t)(dst)), "l"((const void*)(src)) : "memory")
#define CP_COMMIT() asm volatile("cp.async.commit_group;" ::: "memory")
#define CP_WAIT0()  asm volatile("cp.async.wait_group 0;" ::: "memory")
#define LDSM4(r0,r1,r2,r3,a) asm volatile( \
    "ldmatrix.sync.aligned.m8n8.x4.shared.b16 {%0,%1,%2,%3}, [%4];" \
    : "=r"(r0),"=r"(r1),"=r"(r2),"=r"(r3) : "r"(a))
#define MMA16816(c,a,b) asm volatile( \
    "mma.sync.aligned.m16n8k16.row.col.f32.bf16.bf16.f32 " \
    "{%0,%1,%2,%3},{%4,%5,%6,%7},{%8,%9},{%0,%1,%2,%3};" \
    : "+f"((c)[0]),"+f"((c)[1]),"+f"((c)[2]),"+f"((c)[3]) \
    : "r"((a)[0]),"r"((a)[1]),"r"((a)[2]),"r"((a)[3]), "r"((b)[0]),"r"((b)[1]))

__device__ __forceinline__ unsigned pack_hi(float v0, float v1, unsigned& lp){
    unsigned hp; asm("cvt.rn.bf16x2.f32 %0, %1, %2;" : "=r"(hp) : "f"(v1), "f"(v0));
    float h0 = __uint_as_float(hp << 16);
    float h1 = __uint_as_float(hp & 0xffff0000u);
    asm("cvt.rn.bf16x2.f32 %0, %1, %2;" : "=r"(lp) : "f"(v1-h1), "f"(v0-h0));
    return hp;
}
__device__ __forceinline__ void split1(float v, unsigned short& h, unsigned short& lo){
    __nv_bfloat16 bh = __float2bfloat16(v);
    float hf = __bfloat162float(bh);
    __nv_bfloat16 bl = __float2bfloat16(v - hf);
    h = __bfloat16_as_ushort(bh); lo = __bfloat16_as_ushort(bl);
}

// 128x128x128 GEMM, 3-pass hi/lo. A panels [2][128][64] at aoff (hi) / aoff+32768 (lo),
// B panels [2][128][64] at boff / boff+32768. Warp grid 2(M)x4(N), per-warp 64x32.
__device__ __forceinline__ void gemm128(uint32_t sb, uint32_t aoff, uint32_t boff,
                                        int l, int mw, int nw, float acc[4][4][4])
{
#pragma unroll
    for (int pn = 0; pn < 2; pn++){
#pragma unroll
        for (int ks = 0; ks < 4; ks++){
            uint32_t ah[4][4], al[4][4], bh[4][2], bl[4][2];
            const uint32_t abyte = ks*32 + ((l>>4)<<4);
#pragma unroll
            for (int f = 0; f < 4; f++){
                int row = mw*64 + f*16 + (l & 15);
                uint32_t off = pn*16384 + SWZ((uint32_t)(row*128) + abyte);
                LDSM4(ah[f][0],ah[f][1],ah[f][2],ah[f][3], sb + aoff + off);
                LDSM4(al[f][0],al[f][1],al[f][2],al[f][3], sb + aoff + 32768 + off);
            }
            const uint32_t bbyte = ks*32 + (((l>>3)&1)<<4);
#pragma unroll
            for (int g2 = 0; g2 < 2; g2++){
                int rowb = nw*32 + g2*16 + (l & 7) + ((l>>4)<<3);
                uint32_t off = pn*16384 + SWZ((uint32_t)(rowb*128) + bbyte);
                uint32_t t0,t1,t2,t3;
                LDSM4(t0,t1,t2,t3, sb + boff + off);
                bh[g2*2][0]=t0; bh[g2*2][1]=t1; bh[g2*2+1][0]=t2; bh[g2*2+1][1]=t3;
                LDSM4(t0,t1,t2,t3, sb + boff + 32768 + off);
                bl[g2*2][0]=t0; bl[g2*2][1]=t1; bl[g2*2+1][0]=t2; bl[g2*2+1][1]=t3;
            }
#pragma unroll
            for (int f = 0; f < 4; f++)
#pragma unroll
                for (int g = 0; g < 4; g++){
                    MMA16816(acc[f][g], ah[f], bh[g]);
                    MMA16816(acc[f][g], ah[f], bl[g]);
                    MMA16816(acc[f][g], al[f], bh[g]);
                }
        }
    }
}

__device__ __forceinline__ void block_reduce_2(float& s, float& q, float* red)
{
#pragma unroll
    for (int off=16; off>0; off>>=1){
        s += __shfl_down_sync(0xffffffffu, s, off);
        q += __shfl_down_sync(0xffffffffu, q, off);
    }
    const int wid = threadIdx.x >> 5;
    if ((threadIdx.x & 31) == 0){ red[wid] = s; red[8+wid] = q; }
    __syncthreads();
    s = 0.f; q = 0.f;
#pragma unroll
    for (int i=0;i<8;i++){ s += red[i]; q += red[8+i]; }
    __syncthreads();
}

// ============ transpose+convert inputs: [b][c][h][w] -> [inp][b][h][w][c] hi/lo ====
__global__ __launch_bounds__(256) void xpose_cvt(const float* __restrict__ x,
    const float* __restrict__ xf, const float* __restrict__ xr)
{
    extern __shared__ float tl[];   // [128][133]
    const int inp = blockIdx.x, h = blockIdx.y, b = blockIdx.z;
    const float* src = inp==0 ? x : (inp==1 ? xf : xr);
    const int tid = threadIdx.x;
    const float* sp = src + (size_t)b*CHW + (size_t)h*128;
    for (int u = tid; u < 4096; u += 256){
        int c = u >> 5, q = u & 31;
        float4 v = *(const float4*)(sp + (size_t)c*HW + 4*q);
        float* d = tl + c*133 + 4*q;
        d[0]=v.x; d[1]=v.y; d[2]=v.z; d[3]=v.w;
    }
    __syncthreads();
    const size_t obase = ((size_t)inp*1024 + b*128 + h) * 16384;
    for (int u = tid; u < 4096; u += 256){
        int cg = u & 31, w = u >> 5;
        float v0 = tl[(4*cg+0)*133 + w], v1 = tl[(4*cg+1)*133 + w];
        float v2 = tl[(4*cg+2)*133 + w], v3 = tl[(4*cg+3)*133 + w];
        unsigned lp0, lp1;
        unsigned hp0 = pack_hi(v0, v1, lp0);
        unsigned hp1 = pack_hi(v2, v3, lp1);
        size_t o = obase + (size_t)w*128 + 4*cg;
        *(uint2*)&g_tih[o] = make_uint2(hp0, hp1);
        *(uint2*)&g_til[o] = make_uint2(lp0, lp1);
    }
}

// ============ compose 1x1 weights: which 0:Wx 1:W1@Wx 2:W2@Wx 3:Wf 4:Wr =====
__global__ __launch_bounds__(256) void wcompose_kernel(
    const float* __restrict__ Wx, const float* __restrict__ bx,
    const float* __restrict__ W1, const float* __restrict__ b1,
    const float* __restrict__ W2, const float* __restrict__ b2,
    const float* __restrict__ Wf, const float* __restrict__ bf,
    const float* __restrict__ Wr, const float* __restrict__ br_)
{
    extern __shared__ float S[];    // 16384 floats
    const int which = blockIdx.x, tid = threadIdx.x;
    if (which == 0 || which >= 3){
        const float* Ws = which==0 ? Wx : (which==3 ? Wf : Wr);
        const float* bs = which==0 ? bx : (which==3 ? bf : br_);
        for (int i = tid; i < 16384; i += 256) g_wcf[which*16384 + i] = Ws[i];
        if (tid < 128) g_bcf[which*128 + tid] = bs[tid];
        return;
    }
    const float* Wo = (which==1) ? W1 : W2;
    const float* bo = (which==1) ? b1 : b2;
    for (int i = tid; i < 16384; i += 256) S[i] = Wx[i];
    __syncthreads();
    int r = tid >> 1, c0 = (tid & 1) * 64;
    float acc[64];
#pragma unroll
    for (int j = 0; j < 64; j++) acc[j] = 0.f;
    for (int k = 0; k < 128; k++){
        float a = Wo[r*128 + k];
#pragma unroll
        for (int j = 0; j < 64; j++) acc[j] = fmaf(a, S[k*128 + c0 + j], acc[j]);
    }
    for (int j = 0; j < 64; j++) g_wcf[which*16384 + r*128 + c0 + j] = acc[j];
    if (tid < 128){
        float s = bo[tid];
        for (int k = 0; k < 128; k++) s = fmaf(Wo[tid*128 + k], bx[k], s);
        g_bcf[which*128 + tid] = s;
    }
}

// split composed weights to hi/lo panels [which][pn][o][ci64]
__global__ void wsplit_kernel()
{
    int idx = blockIdx.x*256 + threadIdx.x;        // 81920
    if (idx >= 81920) return;
    int ci = idx & 63, o = (idx >> 6) & 127, pn = (idx >> 13) & 1, which = idx >> 14;
    float v = g_wcf[which*16384 + o*128 + pn*64 + ci];
    split1(v, g_wsh[idx], g_wsl[idx]);
}

// ============ conv1x1 on tensor cores: 5 GEMMs from original inputs =========
__global__ __launch_bounds__(256) void conv1x1_mma(void)
{
    extern __shared__ char dsm[];
    const int tid = threadIdx.x, l = tid & 31, wid = tid >> 5;
    const int mw = wid & 1, nw = wid >> 1;
    const int which = blockIdx.x, h = blockIdx.y, b = blockIdx.z;
    const uint32_t sb = smem_u32(dsm);
    const int inp = (which < 3) ? 0 : which - 2;

    const char* wH = (const char*)g_wsh + which*32768;
    const char* wL = (const char*)g_wsl + which*32768;
    for (int u = tid; u < 2048; u += 256){
        uint32_t d = (u >> 10)*16384 + SWZ((uint32_t)((u & 1023)*16));
        CP16(sb + 0     + d, wH + u*16);
        CP16(sb + 32768 + d, wL + u*16);
    }
    const size_t slab = ((size_t)inp*1024 + b*128 + h)*32768;
    const char* tH = (const char*)g_tih + slab;
    const char* tL = (const char*)g_til + slab;
    for (int u = tid; u < 2048; u += 256){
        int w = u >> 4, j = u & 15;
        uint32_t d = (j>>3)*16384 + SWZ((uint32_t)(w*128 + (j&7)*16));
        CP16(sb + 65536 + d, tH + u*16);
        CP16(sb + 98304 + d, tL + u*16);
    }
    CP_COMMIT(); CP_WAIT0(); __syncthreads();

    float acc[4][4][4];
#pragma unroll
    for (int f=0;f<4;f++)
#pragma unroll
        for (int g=0;g<4;g++)
#pragma unroll
            for (int e=0;e<4;e++) acc[f][g][e] = 0.f;
    gemm128(sb, 0, 65536, l, mw, nw, acc);

    const size_t base = (size_t)(b*128 + h)*16384;
    if (which == 0){
#pragma unroll
        for (int f = 0; f < 4; f++){
            int r1 = mw*64 + f*16 + (l>>2), r2 = r1 + 8;
            float b1v = g_bcf[r1], b2v = g_bcf[r2];
#pragma unroll
            for (int g = 0; g < 4; g++){
                int w = nw*32 + g*8 + 2*(l & 3);
                unsigned short hh, ll;
                split1(acc[f][g][0] + b1v, hh, ll);
                g_xph[base + (size_t)w*128 + r1] = hh; g_xpl[base + (size_t)w*128 + r1] = ll;
                split1(acc[f][g][1] + b1v, hh, ll);
                g_xph[base + (size_t)(w+1)*128 + r1] = hh; g_xpl[base + (size_t)(w+1)*128 + r1] = ll;
                split1(acc[f][g][2] + b2v, hh, ll);
                g_xph[base + (size_t)w*128 + r2] = hh; g_xpl[base + (size_t)w*128 + r2] = ll;
                split1(acc[f][g][3] + b2v, hh, ll);
                g_xph[base + (size_t)(w+1)*128 + r2] = hh; g_xpl[base + (size_t)(w+1)*128 + r2] = ll;
            }
        }
    } else {
        unsigned short *oh, *ol;
        if (which == 1){ oh = g_x1h; ol = g_x1l; }
        else if (which == 2){ oh = g_x2h; ol = g_x2l; }
        else if (which == 3){ oh = g_xfh; ol = g_xfl; }
        else { oh = g_xrh; ol = g_xrl; }
#pragma unroll
        for (int f = 0; f < 4; f++){
            int r1 = mw*64 + f*16 + (l>>2), r2 = r1 + 8;
            float b1v = g_bcf[which*128 + r1], b2v = g_bcf[which*128 + r2];
#pragma unroll
            for (int g = 0; g < 4; g++){
                int w = nw*32 + g*8 + 2*(l & 3);
                unsigned lp;
                unsigned hp = pack_hi(acc[f][g][0] + b1v, acc[f][g][1] + b1v, lp);
                *(unsigned*)&oh[base + (size_t)r1*128 + w] = hp;
                *(unsigned*)&ol[base + (size_t)r1*128 + w] = lp;
                hp = pack_hi(acc[f][g][2] + b2v, acc[f][g][3] + b2v, lp);
                *(unsigned*)&oh[base + (size_t)r2*128 + w] = hp;
                *(unsigned*)&ol[base + (size_t)r2*128 + w] = lp;
            }
        }
    }
}

// ============ attention on tensor cores =====================================
__global__ __launch_bounds__(256) void attn_mma(void)
{
    extern __shared__ char dsm[];
    __shared__ float red[16];
    const int tid = threadIdx.x, l = tid & 31, wid = tid >> 5;
    const int mw = wid & 1, nw = wid >> 1;
    const int br = blockIdx.x, h = blockIdx.y, b = blockIdx.z;
    const uint32_t sb = smem_u32(dsm);
    const size_t slab = (size_t)(b*128 + h) * 32768;
    const char* aH = (const char*)(br ? g_x2h : g_x1h) + slab;
    const char* aL = (const char*)(br ? g_x2l : g_x1l) + slab;
    const char* bH = (const char*)(br ? g_xrh : g_xfh) + slab;
    const char* bL = (const char*)(br ? g_xrl : g_xfl) + slab;

    for (int u = tid; u < 2048; u += 256){
        int c = u >> 4, j = u & 15;
        uint32_t d = (j>>3)*16384 + SWZ((uint32_t)(c*128 + (j&7)*16));
        CP16(sb + 0     + d, aH + u*16);
        CP16(sb + 32768 + d, aL + u*16);
        CP16(sb + 65536 + d, bH + u*16);
        CP16(sb + 98304 + d, bL + u*16);
    }
    CP_COMMIT(); CP_WAIT0(); __syncthreads();

    float acc[4][4][4];
#pragma unroll
    for (int f=0;f<4;f++)
#pragma unroll
        for (int g=0;g<4;g++)
#pragma unroll
            for (int e=0;e<4;e++) acc[f][g][e] = 0.f;
    gemm128(sb, 0, 65536, l, mw, nw, acc);

    float ls = 0.f, lq = 0.f;
#pragma unroll
    for (int f=0;f<4;f++)
#pragma unroll
        for (int g=0;g<4;g++)
#pragma unroll
            for (int e=0;e<4;e++){ ls += acc[f][g][e]; lq += acc[f][g][e]*acc[f][g][e]; }
    block_reduce_2(ls, lq, red);
    float mean = ls * (1.f/16384.f);
    float inv  = rsqrtf(lq * (1.f/16384.f) - mean*mean + EPSF);

    // stage Xp (transposed layout [w][d]) into B region while S-writeback proceeds
    const char* pH = (const char*)g_xph + slab;
    const char* pL = (const char*)g_xpl + slab;
    for (int u = tid; u < 2048; u += 256){
        int w = u >> 4, j = u & 15;
        uint32_t d = (j>>3)*16384 + SWZ((uint32_t)(w*128 + (j&7)*16));
        CP16(sb + 65536 + d, pH + u*16);
        CP16(sb + 98304 + d, pL + u*16);
    }
    CP_COMMIT();

    // write normalized S into A region as panels [c][d64] hi/lo
#pragma unroll
    for (int f = 0; f < 4; f++){
        int c1 = mw*64 + f*16 + (l>>2), c2 = c1 + 8;
#pragma unroll
        for (int g = 0; g < 4; g++){
            int dd = nw*32 + g*8 + 2*(l & 3);
            uint32_t pn = (uint32_t)(dd >> 6)*16384;
            uint32_t byt = (uint32_t)((dd & 63)*2);
            unsigned lp;
            unsigned hp = pack_hi((acc[f][g][0]-mean)*inv, (acc[f][g][1]-mean)*inv, lp);
            *(unsigned*)(dsm + 0     + pn + SWZ((uint32_t)(c1*128) + byt)) = hp;
            *(unsigned*)(dsm + 32768 + pn + SWZ((uint32_t)(c1*128) + byt)) = lp;
            hp = pack_hi((acc[f][g][2]-mean)*inv, (acc[f][g][3]-mean)*inv, lp);
            *(unsigned*)(dsm + 0     + pn + SWZ((uint32_t)(c2*128) + byt)) = hp;
            *(unsigned*)(dsm + 32768 + pn + SWZ((uint32_t)(c2*128) + byt)) = lp;
        }
    }
    CP_WAIT0(); __syncthreads();

#pragma unroll
    for (int f=0;f<4;f++)
#pragma unroll
        for (int g=0;g<4;g++)
#pragma unroll
            for (int e=0;e<4;e++) acc[f][g][e] = 0.f;
    gemm128(sb, 0, 65536, l, mw, nw, acc);

    ls = 0.f; lq = 0.f;
#pragma unroll
    for (int f=0;f<4;f++)
#pragma unroll
        for (int g=0;g<4;g++)
#pragma unroll
            for (int e=0;e<4;e++){ ls += acc[f][g][e]; lq += acc[f][g][e]*acc[f][g][e]; }
    block_reduce_2(ls, lq, red);
    mean = ls * (1.f/16384.f);
    inv  = rsqrtf(lq * (1.f/16384.f) - mean*mean + EPSF);

    const int co = br << 7;
#pragma unroll
    for (int f = 0; f < 4; f++){
        int c1 = mw*64 + f*16 + (l>>2), c2 = c1 + 8;
        float* r1p = g_cat + ((size_t)b*256 + co + c1)*HW + (size_t)h*128;
        float* r2p = g_cat + ((size_t)b*256 + co + c2)*HW + (size_t)h*128;
#pragma unroll
        for (int g = 0; g < 4; g++){
            int w = nw*32 + g*8 + 2*(l & 3);
            float2 v;
            v.x = (acc[f][g][0]-mean)*inv; v.y = (acc[f][g][1]-mean)*inv;
            *(float2*)(r1p + w) = v;
            v.x = (acc[f][g][2]-mean)*inv; v.y = (acc[f][g][3]-mean)*inv;
            *(float2*)(r2p + w) = v;
        }
    }
}

// ============ conv3x3 weight pre-split ======================================
__global__ void presplit_kernel(const float* __restrict__ Wm)
{
    int idx = blockIdx.x*256 + threadIdx.x;      // 9*6*384*64 = 1327104
    if (idx >= 9*6*384*64) return;
    int ci = idx & 63;
    int o  = (idx >> 6) % 384;
    int r  = idx >> 6; r /= 384;
    int chunk = r % 6, tap = r / 6;
    float v = Wm[(size_t)o*3456 + (chunk*64 + ci)*9 + tap];
    split1(v, g_wh[idx], g_wl[idx]);
}

// ===== conv3x3 input to channels-last hi/lo: [b][hp][wp][ci] ================
__global__ __launch_bounds__(256) void padcvt_kernel(const float* __restrict__ x)
{
    __shared__ float tile[64*129];
    const int c0 = blockIdx.x << 6, h = blockIdx.y, b = blockIdx.z;
    const int tid = threadIdx.x;
    for (int idx = tid; idx < 64*128; idx += 256){
        int ci = idx >> 7, w = idx & 127;
        int cg = c0 + ci;
        float v = (cg < 256)
            ? g_cat[((size_t)b*256 + cg)*HW + h*128 + w]
            : x[((size_t)b*128 + (cg-256))*HW + h*128 + w];
        tile[ci*129 + w] = v;
    }
    __syncthreads();
    const size_t obase = (((size_t)b*130 + (h+1))*130)*384;
    for (int idx = tid; idx < 128*8; idx += 256){
        int w = idx >> 3, u = idx & 7;
        unsigned Hp[4], Lp[4];
#pragma unroll
        for (int e2 = 0; e2 < 4; e2++){
            float v0 = tile[(u*8 + 2*e2    )*129 + w];
            float v1 = tile[(u*8 + 2*e2 + 1)*129 + w];
            Hp[e2] = pack_hi(v0, v1, Lp[e2]);
        }
        size_t off2 = (obase + (size_t)(w+1)*384 + c0 + u*8) * 2;
        *(uint4*)((char*)g_bhi + off2) = make_uint4(Hp[0],Hp[1],Hp[2],Hp[3]);
        *(uint4*)((char*)g_blo + off2) = make_uint4(Lp[0],Lp[1],Lp[2],Lp[3]);
    }
}

// =================== conv3x3 via mma.sync bf16 (hi/lo) ======================
#define OFF_AH 0
#define OFF_AL 16384
#define OFF_BH 32768
#define OFF_BL 50176
#define STAGE  67584

__global__ __launch_bounds__(256) void conv3x3_tc(
    const float* __restrict__ bm, const float* __restrict__ gamma,
    const float* __restrict__ beta, const float* __restrict__ rmean,
    const float* __restrict__ rvar, float* __restrict__ out)
{
    extern __shared__ char dsm[];
    const int tid = threadIdx.x, l = tid & 31, wid = tid >> 5;
    const int mw = wid & 1, nw = wid >> 1;
    const int h = blockIdx.y, o0 = blockIdx.x << 7, b = blockIdx.z;
    const uint32_t sb = smem_u32(dsm);

    float acc[4][4][4];
#pragma unroll
    for (int f=0;f<4;f++)
#pragma unroll
        for (int g=0;g<4;g++)
#pragma unroll
            for (int e=0;e<4;e++) acc[f][g][e] = 0.f;

    auto stage = [&](int it, int st){
        int tap = it/6, chunk = it - tap*6;
        int kh = tap/3;
        uint32_t s0 = sb + st*STAGE;
        const char* srcAh = (const char*)g_wh + (((size_t)tap*6 + chunk)*384 + o0)*128;
        const char* srcAl = (const char*)g_wl + (((size_t)tap*6 + chunk)*384 + o0)*128;
        for (int u = tid; u < 1024; u += 256){
            uint32_t d = SWZ(u*16);
            CP16(s0 + OFF_AH + d, srcAh + u*16);
            CP16(s0 + OFF_AL + d, srcAl + u*16);
        }
        size_t rowbase = ((size_t)b*130 + (h+kh))*130*768 + (size_t)chunk*128;
        const char* BH = (const char*)g_bhi;
        const char* BL = (const char*)g_blo;
        for (int u = tid; u < 1040; u += 256){
            int wp = u >> 3, j = u & 7;
            size_t so = rowbase + (size_t)wp*768 + j*16;
            uint32_t d = SWZ(wp*128 + j*16);
            CP16(s0 + OFF_BH + d, BH + so);
            CP16(s0 + OFF_BL + d, BL + so);
        }
    };

    stage(0, 0); CP_COMMIT(); CP_WAIT0(); __syncthreads();

    for (int it = 0; it < 54; it++){
        const int p = it & 1;
        if (it + 1 < 54){ stage(it+1, 1-p); CP_COMMIT(); }

        const int kw = (it/6) % 3;
        const uint32_t s0 = sb + p*STAGE;
#pragma unroll
        for (int ks = 0; ks < 4; ks++){
            uint32_t ah[4][4], al[4][4], bh[4][2], bl[4][2];
            const uint32_t abyte = ks*32 + ((l>>4)<<4);
#pragma unroll
            for (int f = 0; f < 4; f++){
                int row = mw*64 + f*16 + (l & 15);
                uint32_t off = SWZ((uint32_t)(row*128) + abyte);
                LDSM4(ah[f][0],ah[f][1],ah[f][2],ah[f][3], s0 + OFF_AH + off);
                LDSM4(al[f][0],al[f][1],al[f][2],al[f][3], s0 + OFF_AL + off);
            }
            const uint32_t bbyte = ks*32 + (((l>>3)&1)<<4);
#pragma unroll
            for (int g2 = 0; g2 < 2; g2++){
                int rowb = nw*32 + g2*16 + kw + (l & 7) + ((l>>4)<<3);
                uint32_t off = SWZ((uint32_t)(rowb*128) + bbyte);
                uint32_t t0,t1,t2,t3;
                LDSM4(t0,t1,t2,t3, s0 + OFF_BH + off);
                bh[g2*2][0]=t0; bh[g2*2][1]=t1; bh[g2*2+1][0]=t2; bh[g2*2+1][1]=t3;
                LDSM4(t0,t1,t2,t3, s0 + OFF_BL + off);
                bl[g2*2][0]=t0; bl[g2*2][1]=t1; bl[g2*2+1][0]=t2; bl[g2*2+1][1]=t3;
            }
#pragma unroll
            for (int f = 0; f < 4; f++)
#pragma unroll
                for (int g = 0; g < 4; g++){
                    MMA16816(acc[f][g], ah[f], bh[g]);
                    MMA16816(acc[f][g], ah[f], bl[g]);
                    MMA16816(acc[f][g], al[f], bh[g]);
                }
        }
        CP_WAIT0();
        __syncthreads();
    }

#pragma unroll
    for (int f = 0; f < 4; f++){
        int o1 = o0 + mw*64 + f*16 + (l >> 2);
        int o2 = o1 + 8;
        float sc1 = gamma[o1] * rsqrtf(rvar[o1] + EPSF);
        float sh1 = beta[o1] + (bm[o1] - rmean[o1]) * sc1;
        float sc2 = gamma[o2] * rsqrtf(rvar[o2] + EPSF);
        float sh2 = beta[o2] + (bm[o2] - rmean[o2]) * sc2;
        float* r1 = out + ((size_t)(b*384 + o1))*HW + (size_t)h*128;
        float* r2 = out + ((size_t)(b*384 + o2))*HW + (size_t)h*128;
#pragma unroll
        for (int g = 0; g < 4; g++){
            int w = nw*32 + g*8 + 2*(l & 3);
            float2 v1, v2;
            v1.x = fmaxf(fmaf(acc[f][g][0], sc1, sh1), 0.f);
            v1.y = fmaxf(fmaf(acc[f][g][1], sc1, sh1), 0.f);
            v2.x = fmaxf(fmaf(acc[f][g][2], sc2, sh2), 0.f);
            v2.y = fmaxf(fmaf(acc[f][g][3], sc2, sh2), 0.f);
            *(float2*)(r1 + w) = v1;
            *(float2*)(r2 + w) = v2;
        }
    }
}

// =============================================================================
extern "C" void kernel_launch(void* const* d_in, const int* in_sizes, int n_in,
                              void* d_out, int out_size)
{
    const float* x  = (const float*)d_in[0];
    const float* xf = (const float*)d_in[1];
    const float* xr = (const float*)d_in[2];
    const float* Wx = (const float*)d_in[3];
    const float* bx = (const float*)d_in[4];
    const float* W1 = (const float*)d_in[5];
    const float* b1 = (const float*)d_in[6];
    const float* W2 = (const float*)d_in[7];
    const float* b2 = (const float*)d_in[8];
    const float* Wf = (const float*)d_in[9];
    const float* bf = (const float*)d_in[10];
    const float* Wr = (const float*)d_in[11];
    const float* br_ = (const float*)d_in[12];
    const float* Wm = (const float*)d_in[13];
    const float* bm = (const float*)d_in[14];
    const float* gamma = (const float*)d_in[15];
    const float* beta  = (const float*)d_in[16];
    const float* rmean = (const float*)d_in[17];
    const float* rvar  = (const float*)d_in[18];
    float* out = (float*)d_out;

    cudaFuncSetAttribute(xpose_cvt,   cudaFuncAttributeMaxDynamicSharedMemorySize, 68096);
    cudaFuncSetAttribute(wcompose_kernel, cudaFuncAttributeMaxDynamicSharedMemorySize, 65536);
    cudaFuncSetAttribute(conv1x1_mma, cudaFuncAttributeMaxDynamicSharedMemorySize, 131072);
    cudaFuncSetAttribute(attn_mma,    cudaFuncAttributeMaxDynamicSharedMemorySize, 131072);
    cudaFuncSetAttribute(conv3x3_tc,  cudaFuncAttributeMaxDynamicSharedMemorySize, 2*STAGE);

    xpose_cvt<<<dim3(3, 128, 8), 256, 68096>>>(x, xf, xr);
    wcompose_kernel<<<5, 256, 65536>>>(Wx, bx, W1, b1, W2, b2, Wf, bf, Wr, br_);
    wsplit_kernel<<<320, 256>>>();
    conv1x1_mma<<<dim3(5, 128, 8), 256, 131072>>>();
    attn_mma<<<dim3(2, 128, 8), 256, 131072>>>();
    presplit_kernel<<<5184, 256>>>(Wm);
    padcvt_kernel<<<dim3(6, 128, 8), 256>>>(x);
    conv3x3_tc<<<dim3(3, 128, 8), 256, 2*STAGE>>>(bm, gamma, beta, rmean, rvar, out);
}

// round 7
// speedup vs baseline: 6.6832x; 1.9745x over previous
#include <cuda_runtime.h>
#include <cuda_bf16.h>
#include <cuda_fp16.h>
#include <cstdint>

#define EPSF 1e-5f
#define HW   16384
#define CHW  2097152

// ---------------- scratch (static device memory) ----------------
__device__ float g_cat[8*256*HW];                       // attn outputs fp32 (b,2c,h,w)
__device__ float g_wcf[5*16384];                        // composed 1x1 weights fp32
__device__ float g_bcf[5*128];                          // composed biases
__device__ __align__(16) unsigned short g_wsh[5*2*128*64];  // [which][pn][o][ci64] hi
__device__ __align__(16) unsigned short g_wsl[5*2*128*64];
__device__ __align__(16) unsigned short g_tih[3ull*8*CHW];  // inputs T: [inp][b][h][w][c] hi
__device__ __align__(16) unsigned short g_til[3ull*8*CHW];
__device__ __align__(16) unsigned short g_x1h[8*CHW], g_x1l[8*CHW];  // [b][h][c][w]
__device__ __align__(16) unsigned short g_x2h[8*CHW], g_x2l[8*CHW];
__device__ __align__(16) unsigned short g_xfh[8*CHW], g_xfl[8*CHW];
__device__ __align__(16) unsigned short g_xrh[8*CHW], g_xrl[8*CHW];
__device__ __align__(16) unsigned short g_xph[8*CHW], g_xpl[8*CHW];  // [b][h][w][d]
__device__ unsigned short g_wh[9*6*384*64];             // conv3x3 W fp16: [tap][chunk][o][ci]
__device__ unsigned short g_bhi[8ull*130*130*384];      // conv3x3 in fp16: [b][hp][wp][ci]

// ---------------- helpers ----------------
__device__ __forceinline__ uint32_t smem_u32(const void* p){
    uint32_t a; asm("{ .reg .u64 t; cvta.to.shared.u64 t, %1; cvt.u32.u64 %0, t; }"
                    : "=r"(a) : "l"(p)); return a;
}
#define SWZ(x) ((x) ^ (((x)>>3)&0x70))
#define CP16(dst, src) asm volatile("cp.async.cg.shared.global [%0], [%1], 16;" \
    :: "r"((uint32_t)(dst)), "l"((const void*)(src)) : "memory")
#define CP_COMMIT() asm volatile("cp.async.commit_group;" ::: "memory")
#define CP_WAIT0()  asm volatile("cp.async.wait_group 0;" ::: "memory")
#define LDSM4(r0,r1,r2,r3,a) asm volatile( \
    "ldmatrix.sync.aligned.m8n8.x4.shared.b16 {%0,%1,%2,%3}, [%4];" \
    : "=r"(r0),"=r"(r1),"=r"(r2),"=r"(r3) : "r"(a))
#define MMA16816(c,a,b) asm volatile( \
    "mma.sync.aligned.m16n8k16.row.col.f32.bf16.bf16.f32 " \
    "{%0,%1,%2,%3},{%4,%5,%6,%7},{%8,%9},{%0,%1,%2,%3};" \
    : "+f"((c)[0]),"+f"((c)[1]),"+f"((c)[2]),"+f"((c)[3]) \
    : "r"((a)[0]),"r"((a)[1]),"r"((a)[2]),"r"((a)[3]), "r"((b)[0]),"r"((b)[1]))
#define MMAF16(c,a,b) asm volatile( \
    "mma.sync.aligned.m16n8k16.row.col.f32.f16.f16.f32 " \
    "{%0,%1,%2,%3},{%4,%5,%6,%7},{%8,%9},{%0,%1,%2,%3};" \
    : "+f"((c)[0]),"+f"((c)[1]),"+f"((c)[2]),"+f"((c)[3]) \
    : "r"((a)[0]),"r"((a)[1]),"r"((a)[2]),"r"((a)[3]), "r"((b)[0]),"r"((b)[1]))

__device__ __forceinline__ unsigned pack_hi(float v0, float v1, unsigned& lp){
    unsigned hp; asm("cvt.rn.bf16x2.f32 %0, %1, %2;" : "=r"(hp) : "f"(v1), "f"(v0));
    float h0 = __uint_as_float(hp << 16);
    float h1 = __uint_as_float(hp & 0xffff0000u);
    asm("cvt.rn.bf16x2.f32 %0, %1, %2;" : "=r"(lp) : "f"(v1-h1), "f"(v0-h0));
    return hp;
}
__device__ __forceinline__ unsigned pack_f16(float v0, float v1){
    unsigned hp; asm("cvt.rn.f16x2.f32 %0, %1, %2;" : "=r"(hp) : "f"(v1), "f"(v0));
    return hp;
}
__device__ __forceinline__ void split1(float v, unsigned short& h, unsigned short& lo){
    __nv_bfloat16 bh = __float2bfloat16(v);
    float hf = __bfloat162float(bh);
    __nv_bfloat16 bl = __float2bfloat16(v - hf);
    h = __bfloat16_as_ushort(bh); lo = __bfloat16_as_ushort(bl);
}

// 128x128x128 GEMM, 3-pass hi/lo bf16. A panels at aoff/aoff+32768, B at boff/boff+32768.
__device__ __forceinline__ void gemm128(uint32_t sb, uint32_t aoff, uint32_t boff,
                                        int l, int mw, int nw, float acc[4][4][4])
{
#pragma unroll
    for (int pn = 0; pn < 2; pn++){
#pragma unroll
        for (int ks = 0; ks < 4; ks++){
            uint32_t ah[4][4], al[4][4], bh[4][2], bl[4][2];
            const uint32_t abyte = ks*32 + ((l>>4)<<4);
#pragma unroll
            for (int f = 0; f < 4; f++){
                int row = mw*64 + f*16 + (l & 15);
                uint32_t off = pn*16384 + SWZ((uint32_t)(row*128) + abyte);
                LDSM4(ah[f][0],ah[f][1],ah[f][2],ah[f][3], sb + aoff + off);
                LDSM4(al[f][0],al[f][1],al[f][2],al[f][3], sb + aoff + 32768 + off);
            }
            const uint32_t bbyte = ks*32 + (((l>>3)&1)<<4);
#pragma unroll
            for (int g2 = 0; g2 < 2; g2++){
                int rowb = nw*32 + g2*16 + (l & 7) + ((l>>4)<<3);
                uint32_t off = pn*16384 + SWZ((uint32_t)(rowb*128) + bbyte);
                uint32_t t0,t1,t2,t3;
                LDSM4(t0,t1,t2,t3, sb + boff + off);
                bh[g2*2][0]=t0; bh[g2*2][1]=t1; bh[g2*2+1][0]=t2; bh[g2*2+1][1]=t3;
                LDSM4(t0,t1,t2,t3, sb + boff + 32768 + off);
                bl[g2*2][0]=t0; bl[g2*2][1]=t1; bl[g2*2+1][0]=t2; bl[g2*2+1][1]=t3;
            }
#pragma unroll
            for (int f = 0; f < 4; f++)
#pragma unroll
                for (int g = 0; g < 4; g++){
                    MMA16816(acc[f][g], ah[f], bh[g]);
                    MMA16816(acc[f][g], ah[f], bl[g]);
                    MMA16816(acc[f][g], al[f], bh[g]);
                }
        }
    }
}

__device__ __forceinline__ void block_reduce_2(float& s, float& q, float* red)
{
#pragma unroll
    for (int off=16; off>0; off>>=1){
        s += __shfl_down_sync(0xffffffffu, s, off);
        q += __shfl_down_sync(0xffffffffu, q, off);
    }
    const int wid = threadIdx.x >> 5;
    if ((threadIdx.x & 31) == 0){ red[wid] = s; red[8+wid] = q; }
    __syncthreads();
    s = 0.f; q = 0.f;
#pragma unroll
    for (int i=0;i<8;i++){ s += red[i]; q += red[8+i]; }
    __syncthreads();
}

// ============ transpose+convert inputs: [b][c][h][w] -> [inp][b][h][w][c] hi/lo ====
__global__ __launch_bounds__(256) void xpose_cvt(const float* __restrict__ x,
    const float* __restrict__ xf, const float* __restrict__ xr)
{
    extern __shared__ float tl[];   // [128][133]
    const int inp = blockIdx.x, h = blockIdx.y, b = blockIdx.z;
    const float* src = inp==0 ? x : (inp==1 ? xf : xr);
    const int tid = threadIdx.x;
    const float* sp = src + (size_t)b*CHW + (size_t)h*128;
    for (int u = tid; u < 4096; u += 256){
        int c = u >> 5, q = u & 31;
        float4 v = *(const float4*)(sp + (size_t)c*HW + 4*q);
        float* d = tl + c*133 + 4*q;
        d[0]=v.x; d[1]=v.y; d[2]=v.z; d[3]=v.w;
    }
    __syncthreads();
    const size_t obase = ((size_t)inp*1024 + b*128 + h) * 16384;
    for (int u = tid; u < 4096; u += 256){
        int cg = u & 31, w = u >> 5;
        float v0 = tl[(4*cg+0)*133 + w], v1 = tl[(4*cg+1)*133 + w];
        float v2 = tl[(4*cg+2)*133 + w], v3 = tl[(4*cg+3)*133 + w];
        unsigned lp0, lp1;
        unsigned hp0 = pack_hi(v0, v1, lp0);
        unsigned hp1 = pack_hi(v2, v3, lp1);
        size_t o = obase + (size_t)w*128 + 4*cg;
        *(uint2*)&g_tih[o] = make_uint2(hp0, hp1);
        *(uint2*)&g_til[o] = make_uint2(lp0, lp1);
    }
}

// ============ compose 1x1 weights: which 0:Wx 1:W1@Wx 2:W2@Wx 3:Wf 4:Wr =====
__global__ __launch_bounds__(256) void wcompose_kernel(
    const float* __restrict__ Wx, const float* __restrict__ bx,
    const float* __restrict__ W1, const float* __restrict__ b1,
    const float* __restrict__ W2, const float* __restrict__ b2,
    const float* __restrict__ Wf, const float* __restrict__ bf,
    const float* __restrict__ Wr, const float* __restrict__ br_)
{
    extern __shared__ float S[];    // 16384 floats
    const int which = blockIdx.x, tid = threadIdx.x;
    if (which == 0 || which >= 3){
        const float* Ws = which==0 ? Wx : (which==3 ? Wf : Wr);
        const float* bs = which==0 ? bx : (which==3 ? bf : br_);
        for (int i = tid; i < 16384; i += 256) g_wcf[which*16384 + i] = Ws[i];
        if (tid < 128) g_bcf[which*128 + tid] = bs[tid];
        return;
    }
    const float* Wo = (which==1) ? W1 : W2;
    const float* bo = (which==1) ? b1 : b2;
    for (int i = tid; i < 16384; i += 256) S[i] = Wx[i];
    __syncthreads();
    int r = tid >> 1, c0 = (tid & 1) * 64;
    float acc[64];
#pragma unroll
    for (int j = 0; j < 64; j++) acc[j] = 0.f;
    for (int k = 0; k < 128; k++){
        float a = Wo[r*128 + k];
#pragma unroll
        for (int j = 0; j < 64; j++) acc[j] = fmaf(a, S[k*128 + c0 + j], acc[j]);
    }
    for (int j = 0; j < 64; j++) g_wcf[which*16384 + r*128 + c0 + j] = acc[j];
    if (tid < 128){
        float s = bo[tid];
        for (int k = 0; k < 128; k++) s = fmaf(Wo[tid*128 + k], bx[k], s);
        g_bcf[which*128 + tid] = s;
    }
}

// split composed weights to hi/lo panels [which][pn][o][ci64]
__global__ void wsplit_kernel()
{
    int idx = blockIdx.x*256 + threadIdx.x;        // 81920
    if (idx >= 81920) return;
    int ci = idx & 63, o = (idx >> 6) & 127, pn = (idx >> 13) & 1, which = idx >> 14;
    float v = g_wcf[which*16384 + o*128 + pn*64 + ci];
    split1(v, g_wsh[idx], g_wsl[idx]);
}

// ============ conv1x1 on tensor cores: 5 GEMMs from original inputs =========
__global__ __launch_bounds__(256) void conv1x1_mma(void)
{
    extern __shared__ char dsm[];
    const int tid = threadIdx.x, l = tid & 31, wid = tid >> 5;
    const int mw = wid & 1, nw = wid >> 1;
    const int which = blockIdx.x, h = blockIdx.y, b = blockIdx.z;
    const uint32_t sb = smem_u32(dsm);
    const int inp = (which < 3) ? 0 : which - 2;

    const char* wH = (const char*)g_wsh + which*32768;
    const char* wL = (const char*)g_wsl + which*32768;
    for (int u = tid; u < 2048; u += 256){
        uint32_t d = (u >> 10)*16384 + SWZ((uint32_t)((u & 1023)*16));
        CP16(sb + 0     + d, wH + u*16);
        CP16(sb + 32768 + d, wL + u*16);
    }
    const size_t slab = ((size_t)inp*1024 + b*128 + h)*32768;
    const char* tH = (const char*)g_tih + slab;
    const char* tL = (const char*)g_til + slab;
    for (int u = tid; u < 2048; u += 256){
        int w = u >> 4, j = u & 15;
        uint32_t d = (j>>3)*16384 + SWZ((uint32_t)(w*128 + (j&7)*16));
        CP16(sb + 65536 + d, tH + u*16);
        CP16(sb + 98304 + d, tL + u*16);
    }
    CP_COMMIT(); CP_WAIT0(); __syncthreads();

    float acc[4][4][4];
#pragma unroll
    for (int f=0;f<4;f++)
#pragma unroll
        for (int g=0;g<4;g++)
#pragma unroll
            for (int e=0;e<4;e++) acc[f][g][e] = 0.f;
    gemm128(sb, 0, 65536, l, mw, nw, acc);

    const size_t base = (size_t)(b*128 + h)*16384;
    if (which == 0){
#pragma unroll
        for (int f = 0; f < 4; f++){
            int r1 = mw*64 + f*16 + (l>>2), r2 = r1 + 8;
            float b1v = g_bcf[r1], b2v = g_bcf[r2];
#pragma unroll
            for (int g = 0; g < 4; g++){
                int w = nw*32 + g*8 + 2*(l & 3);
                unsigned short hh, ll;
                split1(acc[f][g][0] + b1v, hh, ll);
                g_xph[base + (size_t)w*128 + r1] = hh; g_xpl[base + (size_t)w*128 + r1] = ll;
                split1(acc[f][g][1] + b1v, hh, ll);
                g_xph[base + (size_t)(w+1)*128 + r1] = hh; g_xpl[base + (size_t)(w+1)*128 + r1] = ll;
                split1(acc[f][g][2] + b2v, hh, ll);
                g_xph[base + (size_t)w*128 + r2] = hh; g_xpl[base + (size_t)w*128 + r2] = ll;
                split1(acc[f][g][3] + b2v, hh, ll);
                g_xph[base + (size_t)(w+1)*128 + r2] = hh; g_xpl[base + (size_t)(w+1)*128 + r2] = ll;
            }
        }
    } else {
        unsigned short *oh, *ol;
        if (which == 1){ oh = g_x1h; ol = g_x1l; }
        else if (which == 2){ oh = g_x2h; ol = g_x2l; }
        else if (which == 3){ oh = g_xfh; ol = g_xfl; }
        else { oh = g_xrh; ol = g_xrl; }
#pragma unroll
        for (int f = 0; f < 4; f++){
            int r1 = mw*64 + f*16 + (l>>2), r2 = r1 + 8;
            float b1v = g_bcf[which*128 + r1], b2v = g_bcf[which*128 + r2];
#pragma unroll
            for (int g = 0; g < 4; g++){
                int w = nw*32 + g*8 + 2*(l & 3);
                unsigned lp;
                unsigned hp = pack_hi(acc[f][g][0] + b1v, acc[f][g][1] + b1v, lp);
                *(unsigned*)&oh[base + (size_t)r1*128 + w] = hp;
                *(unsigned*)&ol[base + (size_t)r1*128 + w] = lp;
                hp = pack_hi(acc[f][g][2] + b2v, acc[f][g][3] + b2v, lp);
                *(unsigned*)&oh[base + (size_t)r2*128 + w] = hp;
                *(unsigned*)&ol[base + (size_t)r2*128 + w] = lp;
            }
        }
    }
}

// ============ attention on tensor cores =====================================
__global__ __launch_bounds__(256) void attn_mma(void)
{
    extern __shared__ char dsm[];
    __shared__ float red[16];
    const int tid = threadIdx.x, l = tid & 31, wid = tid >> 5;
    const int mw = wid & 1, nw = wid >> 1;
    const int br = blockIdx.x, h = blockIdx.y, b = blockIdx.z;
    const uint32_t sb = smem_u32(dsm);
    const size_t slab = (size_t)(b*128 + h) * 32768;
    const char* aH = (const char*)(br ? g_x2h : g_x1h) + slab;
    const char* aL = (const char*)(br ? g_x2l : g_x1l) + slab;
    const char* bH = (const char*)(br ? g_xrh : g_xfh) + slab;
    const char* bL = (const char*)(br ? g_xrl : g_xfl) + slab;

    for (int u = tid; u < 2048; u += 256){
        int c = u >> 4, j = u & 15;
        uint32_t d = (j>>3)*16384 + SWZ((uint32_t)(c*128 + (j&7)*16));
        CP16(sb + 0     + d, aH + u*16);
        CP16(sb + 32768 + d, aL + u*16);
        CP16(sb + 65536 + d, bH + u*16);
        CP16(sb + 98304 + d, bL + u*16);
    }
    CP_COMMIT(); CP_WAIT0(); __syncthreads();

    float acc[4][4][4];
#pragma unroll
    for (int f=0;f<4;f++)
#pragma unroll
        for (int g=0;g<4;g++)
#pragma unroll
            for (int e=0;e<4;e++) acc[f][g][e] = 0.f;
    gemm128(sb, 0, 65536, l, mw, nw, acc);

    float ls = 0.f, lq = 0.f;
#pragma unroll
    for (int f=0;f<4;f++)
#pragma unroll
        for (int g=0;g<4;g++)
#pragma unroll
            for (int e=0;e<4;e++){ ls += acc[f][g][e]; lq += acc[f][g][e]*acc[f][g][e]; }
    block_reduce_2(ls, lq, red);
    float mean = ls * (1.f/16384.f);
    float inv  = rsqrtf(lq * (1.f/16384.f) - mean*mean + EPSF);

    const char* pH = (const char*)g_xph + slab;
    const char* pL = (const char*)g_xpl + slab;
    for (int u = tid; u < 2048; u += 256){
        int w = u >> 4, j = u & 15;
        uint32_t d = (j>>3)*16384 + SWZ((uint32_t)(w*128 + (j&7)*16));
        CP16(sb + 65536 + d, pH + u*16);
        CP16(sb + 98304 + d, pL + u*16);
    }
    CP_COMMIT();

#pragma unroll
    for (int f = 0; f < 4; f++){
        int c1 = mw*64 + f*16 + (l>>2), c2 = c1 + 8;
#pragma unroll
        for (int g = 0; g < 4; g++){
            int dd = nw*32 + g*8 + 2*(l & 3);
            uint32_t pn = (uint32_t)(dd >> 6)*16384;
            uint32_t byt = (uint32_t)((dd & 63)*2);
            unsigned lp;
            unsigned hp = pack_hi((acc[f][g][0]-mean)*inv, (acc[f][g][1]-mean)*inv, lp);
            *(unsigned*)(dsm + 0     + pn + SWZ((uint32_t)(c1*128) + byt)) = hp;
            *(unsigned*)(dsm + 32768 + pn + SWZ((uint32_t)(c1*128) + byt)) = lp;
            hp = pack_hi((acc[f][g][2]-mean)*inv, (acc[f][g][3]-mean)*inv, lp);
            *(unsigned*)(dsm + 0     + pn + SWZ((uint32_t)(c2*128) + byt)) = hp;
            *(unsigned*)(dsm + 32768 + pn + SWZ((uint32_t)(c2*128) + byt)) = lp;
        }
    }
    CP_WAIT0(); __syncthreads();

#pragma unroll
    for (int f=0;f<4;f++)
#pragma unroll
        for (int g=0;g<4;g++)
#pragma unroll
            for (int e=0;e<4;e++) acc[f][g][e] = 0.f;
    gemm128(sb, 0, 65536, l, mw, nw, acc);

    ls = 0.f; lq = 0.f;
#pragma unroll
    for (int f=0;f<4;f++)
#pragma unroll
        for (int g=0;g<4;g++)
#pragma unroll
            for (int e=0;e<4;e++){ ls += acc[f][g][e]; lq += acc[f][g][e]*acc[f][g][e]; }
    block_reduce_2(ls, lq, red);
    mean = ls * (1.f/16384.f);
    inv  = rsqrtf(lq * (1.f/16384.f) - mean*mean + EPSF);

    const int co = br << 7;
#pragma unroll
    for (int f = 0; f < 4; f++){
        int c1 = mw*64 + f*16 + (l>>2), c2 = c1 + 8;
        float* r1p = g_cat + ((size_t)b*256 + co + c1)*HW + (size_t)h*128;
        float* r2p = g_cat + ((size_t)b*256 + co + c2)*HW + (size_t)h*128;
#pragma unroll
        for (int g = 0; g < 4; g++){
            int w = nw*32 + g*8 + 2*(l & 3);
            float2 v;
            v.x = (acc[f][g][0]-mean)*inv; v.y = (acc[f][g][1]-mean)*inv;
            *(float2*)(r1p + w) = v;
            v.x = (acc[f][g][2]-mean)*inv; v.y = (acc[f][g][3]-mean)*inv;
            *(float2*)(r2p + w) = v;
        }
    }
}

// ============ conv3x3 weight prep: fp16 [tap][chunk][o][ci] =================
__global__ void presplit_kernel(const float* __restrict__ Wm)
{
    int idx = blockIdx.x*256 + threadIdx.x;      // 9*6*384*64 = 1327104
    if (idx >= 9*6*384*64) return;
    int ci = idx & 63;
    int o  = (idx >> 6) % 384;
    int r  = idx >> 6; r /= 384;
    int chunk = r % 6, tap = r / 6;
    float v = Wm[(size_t)o*3456 + (chunk*64 + ci)*9 + tap];
    g_wh[idx] = __half_as_ushort(__float2half(v));
}

// ===== conv3x3 input to channels-last fp16: [b][hp][wp][ci] =================
__global__ __launch_bounds__(256) void padcvt_kernel(const float* __restrict__ x)
{
    __shared__ float tile[64*129];
    const int c0 = blockIdx.x << 6, h = blockIdx.y, b = blockIdx.z;
    const int tid = threadIdx.x;
    for (int idx = tid; idx < 64*128; idx += 256){
        int ci = idx >> 7, w = idx & 127;
        int cg = c0 + ci;
        float v = (cg < 256)
            ? g_cat[((size_t)b*256 + cg)*HW + h*128 + w]
            : x[((size_t)b*128 + (cg-256))*HW + h*128 + w];
        tile[ci*129 + w] = v;
    }
    __syncthreads();
    const size_t obase = (((size_t)b*130 + (h+1))*130)*384;
    for (int idx = tid; idx < 128*8; idx += 256){
        int w = idx >> 3, u = idx & 7;
        unsigned Hp[4];
#pragma unroll
        for (int e2 = 0; e2 < 4; e2++){
            float v0 = tile[(u*8 + 2*e2    )*129 + w];
            float v1 = tile[(u*8 + 2*e2 + 1)*129 + w];
            Hp[e2] = pack_f16(v0, v1);
        }
        size_t off2 = (obase + (size_t)(w+1)*384 + c0 + u*8) * 2;
        *(uint4*)((char*)g_bhi + off2) = make_uint4(Hp[0],Hp[1],Hp[2],Hp[3]);
    }
}

// =================== conv3x3 via mma.sync fp16 single-pass ==================
#define OFF_AH 0
#define OFF_BH 16384
#define STAGE  33792

__global__ __launch_bounds__(256) void conv3x3_tc(
    const float* __restrict__ bm, const float* __restrict__ gamma,
    const float* __restrict__ beta, const float* __restrict__ rmean,
    const float* __restrict__ rvar, float* __restrict__ out)
{
    extern __shared__ char dsm[];
    const int tid = threadIdx.x, l = tid & 31, wid = tid >> 5;
    const int mw = wid & 1, nw = wid >> 1;
    const int h = blockIdx.y, o0 = blockIdx.x << 7, b = blockIdx.z;
    const uint32_t sb = smem_u32(dsm);

    float acc[4][4][4];
#pragma unroll
    for (int f=0;f<4;f++)
#pragma unroll
        for (int g=0;g<4;g++)
#pragma unroll
            for (int e=0;e<4;e++) acc[f][g][e] = 0.f;

    auto stage = [&](int it, int st){
        int tap = it/6, chunk = it - tap*6;
        int kh = tap/3;
        uint32_t s0 = sb + st*STAGE;
        const char* srcAh = (const char*)g_wh + (((size_t)tap*6 + chunk)*384 + o0)*128;
        for (int u = tid; u < 1024; u += 256){
            CP16(s0 + OFF_AH + SWZ(u*16), srcAh + u*16);
        }
        size_t rowbase = ((size_t)b*130 + (h+kh))*130*768 + (size_t)chunk*128;
        const char* BH = (const char*)g_bhi;
        for (int u = tid; u < 1040; u += 256){
            int wp = u >> 3, j = u & 7;
            CP16(s0 + OFF_BH + SWZ(wp*128 + j*16), BH + rowbase + (size_t)wp*768 + j*16);
        }
    };

    stage(0, 0); CP_COMMIT(); CP_WAIT0(); __syncthreads();

    for (int it = 0; it < 54; it++){
        const int p = it & 1;
        if (it + 1 < 54){ stage(it+1, 1-p); CP_COMMIT(); }

        const int kw = (it/6) % 3;
        const uint32_t s0 = sb + p*STAGE;
#pragma unroll
        for (int ks = 0; ks < 4; ks++){
            uint32_t ah[4][4], bh[4][2];
            const uint32_t abyte = ks*32 + ((l>>4)<<4);
#pragma unroll
            for (int f = 0; f < 4; f++){
                int row = mw*64 + f*16 + (l & 15);
                uint32_t off = SWZ((uint32_t)(row*128) + abyte);
                LDSM4(ah[f][0],ah[f][1],ah[f][2],ah[f][3], s0 + OFF_AH + off);
            }
            const uint32_t bbyte = ks*32 + (((l>>3)&1)<<4);
#pragma unroll
            for (int g2 = 0; g2 < 2; g2++){
                int rowb = nw*32 + g2*16 + kw + (l & 7) + ((l>>4)<<3);
                uint32_t off = SWZ((uint32_t)(rowb*128) + bbyte);
                uint32_t t0,t1,t2,t3;
                LDSM4(t0,t1,t2,t3, s0 + OFF_BH + off);
                bh[g2*2][0]=t0; bh[g2*2][1]=t1; bh[g2*2+1][0]=t2; bh[g2*2+1][1]=t3;
            }
#pragma unroll
            for (int f = 0; f < 4; f++)
#pragma unroll
                for (int g = 0; g < 4; g++){
                    MMAF16(acc[f][g], ah[f], bh[g]);
                }
        }
        CP_WAIT0();
        __syncthreads();
    }

#pragma unroll
    for (int f = 0; f < 4; f++){
        int o1 = o0 + mw*64 + f*16 + (l >> 2);
        int o2 = o1 + 8;
        float sc1 = gamma[o1] * rsqrtf(rvar[o1] + EPSF);
        float sh1 = beta[o1] + (bm[o1] - rmean[o1]) * sc1;
        float sc2 = gamma[o2] * rsqrtf(rvar[o2] + EPSF);
        float sh2 = beta[o2] + (bm[o2] - rmean[o2]) * sc2;
        float* r1 = out + ((size_t)(b*384 + o1))*HW + (size_t)h*128;
        float* r2 = out + ((size_t)(b*384 + o2))*HW + (size_t)h*128;
#pragma unroll
        for (int g = 0; g < 4; g++){
            int w = nw*32 + g*8 + 2*(l & 3);
            float2 v1, v2;
            v1.x = fmaxf(fmaf(acc[f][g][0], sc1, sh1), 0.f);
            v1.y = fmaxf(fmaf(acc[f][g][1], sc1, sh1), 0.f);
            v2.x = fmaxf(fmaf(acc[f][g][2], sc2, sh2), 0.f);
            v2.y = fmaxf(fmaf(acc[f][g][3], sc2, sh2), 0.f);
            *(float2*)(r1 + w) = v1;
            *(float2*)(r2 + w) = v2;
        }
    }
}

// =============================================================================
extern "C" void kernel_launch(void* const* d_in, const int* in_sizes, int n_in,
                              void* d_out, int out_size)
{
    const float* x  = (const float*)d_in[0];
    const float* xf = (const float*)d_in[1];
    const float* xr = (const float*)d_in[2];
    const float* Wx = (const float*)d_in[3];
    const float* bx = (const float*)d_in[4];
    const float* W1 = (const float*)d_in[5];
    const float* b1 = (const float*)d_in[6];
    const float* W2 = (const float*)d_in[7];
    const float* b2 = (const float*)d_in[8];
    const float* Wf = (const float*)d_in[9];
    const float* bf = (const float*)d_in[10];
    const float* Wr = (const float*)d_in[11];
    const float* br_ = (const float*)d_in[12];
    const float* Wm = (const float*)d_in[13];
    const float* bm = (const float*)d_in[14];
    const float* gamma = (const float*)d_in[15];
    const float* beta  = (const float*)d_in[16];
    const float* rmean = (const float*)d_in[17];
    const float* rvar  = (const float*)d_in[18];
    float* out = (float*)d_out;

    cudaFuncSetAttribute(xpose_cvt,   cudaFuncAttributeMaxDynamicSharedMemorySize, 68096);
    cudaFuncSetAttribute(wcompose_kernel, cudaFuncAttributeMaxDynamicSharedMemorySize, 65536);
    cudaFuncSetAttribute(conv1x1_mma, cudaFuncAttributeMaxDynamicSharedMemorySize, 131072);
    cudaFuncSetAttribute(attn_mma,    cudaFuncAttributeMaxDynamicSharedMemorySize, 131072);
    cudaFuncSetAttribute(conv3x3_tc,  cudaFuncAttributeMaxDynamicSharedMemorySize, 2*STAGE);

    xpose_cvt<<<dim3(3, 128, 8), 256, 68096>>>(x, xf, xr);
    wcompose_kernel<<<5, 256, 65536>>>(Wx, bx, W1, b1, W2, b2, Wf, bf, Wr, br_);
    wsplit_kernel<<<320, 256>>>();
    conv1x1_mma<<<dim3(5, 128, 8), 256, 131072>>>();
    attn_mma<<<dim3(2, 128, 8), 256, 131072>>>();
    presplit_kernel<<<5184, 256>>>(Wm);
    padcvt_kernel<<<dim3(6, 128, 8), 256>>>(x);
    conv3x3_tc<<<dim3(3, 128, 8), 256, 2*STAGE>>>(bm, gamma, beta, rmean, rvar, out);
}

// round 8
// speedup vs baseline: 7.2374x; 1.0829x over previous
#include <cuda_runtime.h>
#include <cuda_bf16.h>
#include <cuda_fp16.h>
#include <cstdint>

#define EPSF 1e-5f
#define HW   16384
#define CHW  2097152

// ---------------- scratch (static device memory) ----------------
__device__ float g_wcf[5*16384];                        // composed 1x1 weights fp32
__device__ float g_bcf[5*128];                          // composed biases
__device__ __align__(16) unsigned short g_wsh[5*2*128*64];  // [which][pn][o][ci64] hi
__device__ __align__(16) unsigned short g_wsl[5*2*128*64];
__device__ __align__(16) unsigned short g_tih[3ull*8*CHW];  // inputs T: [inp][b][h][w][c] hi
__device__ __align__(16) unsigned short g_til[3ull*8*CHW];
__device__ __align__(16) unsigned short g_x1h[8*CHW], g_x1l[8*CHW];  // [b][h][c][w]
__device__ __align__(16) unsigned short g_x2h[8*CHW], g_x2l[8*CHW];
__device__ __align__(16) unsigned short g_xfh[8*CHW], g_xfl[8*CHW];
__device__ __align__(16) unsigned short g_xrh[8*CHW], g_xrl[8*CHW];
__device__ __align__(16) unsigned short g_xph[8*CHW], g_xpl[8*CHW];  // [b][h][w][d]
__device__ unsigned short g_wh[9*6*384*64];             // conv3x3 W fp16: [tap][chunk][o][ci]
__device__ unsigned short g_bhi[8ull*130*130*384];      // conv3x3 in fp16: [b][hp][wp][ci]

// ---------------- helpers ----------------
__device__ __forceinline__ uint32_t smem_u32(const void* p){
    uint32_t a; asm("{ .reg .u64 t; cvta.to.shared.u64 t, %1; cvt.u32.u64 %0, t; }"
                    : "=r"(a) : "l"(p)); return a;
}
#define SWZ(x) ((x) ^ (((x)>>3)&0x70))
#define CP16(dst, src) asm volatile("cp.async.cg.shared.global [%0], [%1], 16;" \
    :: "r"((uint32_t)(dst)), "l"((const void*)(src)) : "memory")
#define CP_COMMIT() asm volatile("cp.async.commit_group;" ::: "memory")
#define CP_WAIT0()  asm volatile("cp.async.wait_group 0;" ::: "memory")
#define LDSM4(r0,r1,r2,r3,a) asm volatile( \
    "ldmatrix.sync.aligned.m8n8.x4.shared.b16 {%0,%1,%2,%3}, [%4];" \
    : "=r"(r0),"=r"(r1),"=r"(r2),"=r"(r3) : "r"(a))
#define MMA16816(c,a,b) asm volatile( \
    "mma.sync.aligned.m16n8k16.row.col.f32.bf16.bf16.f32 " \
    "{%0,%1,%2,%3},{%4,%5,%6,%7},{%8,%9},{%0,%1,%2,%3};" \
    : "+f"((c)[0]),"+f"((c)[1]),"+f"((c)[2]),"+f"((c)[3]) \
    : "r"((a)[0]),"r"((a)[1]),"r"((a)[2]),"r"((a)[3]), "r"((b)[0]),"r"((b)[1]))
#define MMAF16(c,a,b) asm volatile( \
    "mma.sync.aligned.m16n8k16.row.col.f32.f16.f16.f32 " \
    "{%0,%1,%2,%3},{%4,%5,%6,%7},{%8,%9},{%0,%1,%2,%3};" \
    : "+f"((c)[0]),"+f"((c)[1]),"+f"((c)[2]),"+f"((c)[3]) \
    : "r"((a)[0]),"r"((a)[1]),"r"((a)[2]),"r"((a)[3]), "r"((b)[0]),"r"((b)[1]))

__device__ __forceinline__ unsigned pack_hi(float v0, float v1, unsigned& lp){
    unsigned hp; asm("cvt.rn.bf16x2.f32 %0, %1, %2;" : "=r"(hp) : "f"(v1), "f"(v0));
    float h0 = __uint_as_float(hp << 16);
    float h1 = __uint_as_float(hp & 0xffff0000u);
    asm("cvt.rn.bf16x2.f32 %0, %1, %2;" : "=r"(lp) : "f"(v1-h1), "f"(v0-h0));
    return hp;
}
__device__ __forceinline__ unsigned pack_f16(float v0, float v1){
    unsigned hp; asm("cvt.rn.f16x2.f32 %0, %1, %2;" : "=r"(hp) : "f"(v1), "f"(v0));
    return hp;
}
__device__ __forceinline__ void split1(float v, unsigned short& h, unsigned short& lo){
    __nv_bfloat16 bh = __float2bfloat16(v);
    float hf = __bfloat162float(bh);
    __nv_bfloat16 bl = __float2bfloat16(v - hf);
    h = __bfloat16_as_ushort(bh); lo = __bfloat16_as_ushort(bl);
}

// 128x128x64 GEMM chunk, 3-pass bf16 hi/lo. Panel bases are byte offsets into dsm.
__device__ __forceinline__ void gemm64(uint32_t sb, uint32_t a_hi, uint32_t a_lo,
                                       uint32_t b_hi, uint32_t b_lo,
                                       int l, int mw, int nw, float acc[4][4][4])
{
#pragma unroll
    for (int ks = 0; ks < 4; ks++){
        uint32_t ah[4][4], al[4][4], bh[4][2], bl[4][2];
        const uint32_t abyte = ks*32 + ((l>>4)<<4);
#pragma unroll
        for (int f = 0; f < 4; f++){
            int row = mw*64 + f*16 + (l & 15);
            uint32_t off = SWZ((uint32_t)(row*128) + abyte);
            LDSM4(ah[f][0],ah[f][1],ah[f][2],ah[f][3], sb + a_hi + off);
            LDSM4(al[f][0],al[f][1],al[f][2],al[f][3], sb + a_lo + off);
        }
        const uint32_t bbyte = ks*32 + (((l>>3)&1)<<4);
#pragma unroll
        for (int g2 = 0; g2 < 2; g2++){
            int rowb = nw*32 + g2*16 + (l & 7) + ((l>>4)<<3);
            uint32_t off = SWZ((uint32_t)(rowb*128) + bbyte);
            uint32_t t0,t1,t2,t3;
            LDSM4(t0,t1,t2,t3, sb + b_hi + off);
            bh[g2*2][0]=t0; bh[g2*2][1]=t1; bh[g2*2+1][0]=t2; bh[g2*2+1][1]=t3;
            LDSM4(t0,t1,t2,t3, sb + b_lo + off);
            bl[g2*2][0]=t0; bl[g2*2][1]=t1; bl[g2*2+1][0]=t2; bl[g2*2+1][1]=t3;
        }
#pragma unroll
        for (int f = 0; f < 4; f++)
#pragma unroll
            for (int g = 0; g < 4; g++){
                MMA16816(acc[f][g], ah[f], bh[g]);
                MMA16816(acc[f][g], ah[f], bl[g]);
                MMA16816(acc[f][g], al[f], bh[g]);
            }
    }
}

__device__ __forceinline__ void block_reduce_2(float& s, float& q, float* red)
{
#pragma unroll
    for (int off=16; off>0; off>>=1){
        s += __shfl_down_sync(0xffffffffu, s, off);
        q += __shfl_down_sync(0xffffffffu, q, off);
    }
    const int wid = threadIdx.x >> 5;
    if ((threadIdx.x & 31) == 0){ red[wid] = s; red[8+wid] = q; }
    __syncthreads();
    s = 0.f; q = 0.f;
#pragma unroll
    for (int i=0;i<8;i++){ s += red[i]; q += red[8+i]; }
    __syncthreads();
}

// ============ transpose+convert inputs: [b][c][h][w] -> [inp][b][h][w][c] hi/lo ====
__global__ __launch_bounds__(256) void xpose_cvt(const float* __restrict__ x,
    const float* __restrict__ xf, const float* __restrict__ xr)
{
    extern __shared__ float tl[];   // [128][133]
    const int inp = blockIdx.x, h = blockIdx.y, b = blockIdx.z;
    const float* src = inp==0 ? x : (inp==1 ? xf : xr);
    const int tid = threadIdx.x;
    const float* sp = src + (size_t)b*CHW + (size_t)h*128;
    for (int u = tid; u < 4096; u += 256){
        int c = u >> 5, q = u & 31;
        float4 v = *(const float4*)(sp + (size_t)c*HW + 4*q);
        float* d = tl + c*133 + 4*q;
        d[0]=v.x; d[1]=v.y; d[2]=v.z; d[3]=v.w;
    }
    __syncthreads();
    const size_t obase = ((size_t)inp*1024 + b*128 + h) * 16384;
    for (int u = tid; u < 4096; u += 256){
        int cg = u & 31, w = u >> 5;
        float v0 = tl[(4*cg+0)*133 + w], v1 = tl[(4*cg+1)*133 + w];
        float v2 = tl[(4*cg+2)*133 + w], v3 = tl[(4*cg+3)*133 + w];
        unsigned lp0, lp1;
        unsigned hp0 = pack_hi(v0, v1, lp0);
        unsigned hp1 = pack_hi(v2, v3, lp1);
        size_t o = obase + (size_t)w*128 + 4*cg;
        *(uint2*)&g_tih[o] = make_uint2(hp0, hp1);
        *(uint2*)&g_til[o] = make_uint2(lp0, lp1);
    }
}

// ============ compose 1x1 weights: which 0:Wx 1:W1@Wx 2:W2@Wx 3:Wf 4:Wr =====
__global__ __launch_bounds__(256) void wcompose_kernel(
    const float* __restrict__ Wx, const float* __restrict__ bx,
    const float* __restrict__ W1, const float* __restrict__ b1,
    const float* __restrict__ W2, const float* __restrict__ b2,
    const float* __restrict__ Wf, const float* __restrict__ bf,
    const float* __restrict__ Wr, const float* __restrict__ br_)
{
    extern __shared__ float S[];
    const int which = blockIdx.x, tid = threadIdx.x;
    if (which == 0 || which >= 3){
        const float* Ws = which==0 ? Wx : (which==3 ? Wf : Wr);
        const float* bs = which==0 ? bx : (which==3 ? bf : br_);
        for (int i = tid; i < 16384; i += 256) g_wcf[which*16384 + i] = Ws[i];
        if (tid < 128) g_bcf[which*128 + tid] = bs[tid];
        return;
    }
    const float* Wo = (which==1) ? W1 : W2;
    const float* bo = (which==1) ? b1 : b2;
    for (int i = tid; i < 16384; i += 256) S[i] = Wx[i];
    __syncthreads();
    int r = tid >> 1, c0 = (tid & 1) * 64;
    float acc[64];
#pragma unroll
    for (int j = 0; j < 64; j++) acc[j] = 0.f;
    for (int k = 0; k < 128; k++){
        float a = Wo[r*128 + k];
#pragma unroll
        for (int j = 0; j < 64; j++) acc[j] = fmaf(a, S[k*128 + c0 + j], acc[j]);
    }
    for (int j = 0; j < 64; j++) g_wcf[which*16384 + r*128 + c0 + j] = acc[j];
    if (tid < 128){
        float s = bo[tid];
        for (int k = 0; k < 128; k++) s = fmaf(Wo[tid*128 + k], bx[k], s);
        g_bcf[which*128 + tid] = s;
    }
}

// split composed weights to hi/lo panels [which][pn][o][ci64]
__global__ void wsplit_kernel()
{
    int idx = blockIdx.x*256 + threadIdx.x;
    if (idx >= 81920) return;
    int ci = idx & 63, o = (idx >> 6) & 127, pn = (idx >> 13) & 1, which = idx >> 14;
    float v = g_wcf[which*16384 + o*128 + pn*64 + ci];
    split1(v, g_wsh[idx], g_wsl[idx]);
}

// ============ conv1x1 on tensor cores: split-K, 64KB smem, 2 CTAs/SM ========
__global__ __launch_bounds__(256, 2) void conv1x1_mma(void)
{
    extern __shared__ char dsm[];
    const int tid = threadIdx.x, l = tid & 31, wid = tid >> 5;
    const int mw = wid & 1, nw = wid >> 1;
    const int which = blockIdx.x, h = blockIdx.y, b = blockIdx.z;
    const uint32_t sb = smem_u32(dsm);
    const int inp = (which < 3) ? 0 : which - 2;

    const char* wH = (const char*)g_wsh + which*32768;
    const char* wL = (const char*)g_wsl + which*32768;
    const size_t slab = ((size_t)inp*1024 + b*128 + h)*32768;
    const char* tH = (const char*)g_tih + slab;
    const char* tL = (const char*)g_til + slab;

    auto stage = [&](int pn){
        for (int u = tid; u < 1024; u += 256){
            uint32_t d = SWZ((uint32_t)(u*16));
            CP16(sb + 0     + d, wH + pn*16384 + u*16);
            CP16(sb + 16384 + d, wL + pn*16384 + u*16);
        }
        for (int u = tid; u < 1024; u += 256){
            int w = u >> 3, j = u & 7;
            uint32_t d = SWZ((uint32_t)(w*128 + j*16));
            CP16(sb + 32768 + d, tH + w*256 + pn*128 + j*16);
            CP16(sb + 49152 + d, tL + w*256 + pn*128 + j*16);
        }
    };

    float acc[4][4][4];
#pragma unroll
    for (int f=0;f<4;f++)
#pragma unroll
        for (int g=0;g<4;g++)
#pragma unroll
            for (int e=0;e<4;e++) acc[f][g][e] = 0.f;

    stage(0); CP_COMMIT(); CP_WAIT0(); __syncthreads();
    gemm64(sb, 0, 16384, 32768, 49152, l, mw, nw, acc);
    __syncthreads();
    stage(1); CP_COMMIT(); CP_WAIT0(); __syncthreads();
    gemm64(sb, 0, 16384, 32768, 49152, l, mw, nw, acc);

    const size_t base = (size_t)(b*128 + h)*16384;
    if (which == 0){
#pragma unroll
        for (int f = 0; f < 4; f++){
            int r1 = mw*64 + f*16 + (l>>2), r2 = r1 + 8;
            float b1v = g_bcf[r1], b2v = g_bcf[r2];
#pragma unroll
            for (int g = 0; g < 4; g++){
                int w = nw*32 + g*8 + 2*(l & 3);
                unsigned short hh, ll;
                split1(acc[f][g][0] + b1v, hh, ll);
                g_xph[base + (size_t)w*128 + r1] = hh; g_xpl[base + (size_t)w*128 + r1] = ll;
                split1(acc[f][g][1] + b1v, hh, ll);
                g_xph[base + (size_t)(w+1)*128 + r1] = hh; g_xpl[base + (size_t)(w+1)*128 + r1] = ll;
                split1(acc[f][g][2] + b2v, hh, ll);
                g_xph[base + (size_t)w*128 + r2] = hh; g_xpl[base + (size_t)w*128 + r2] = ll;
                split1(acc[f][g][3] + b2v, hh, ll);
                g_xph[base + (size_t)(w+1)*128 + r2] = hh; g_xpl[base + (size_t)(w+1)*128 + r2] = ll;
            }
        }
    } else {
        unsigned short *oh, *ol;
        if (which == 1){ oh = g_x1h; ol = g_x1l; }
        else if (which == 2){ oh = g_x2h; ol = g_x2l; }
        else if (which == 3){ oh = g_xfh; ol = g_xfl; }
        else { oh = g_xrh; ol = g_xrl; }
#pragma unroll
        for (int f = 0; f < 4; f++){
            int r1 = mw*64 + f*16 + (l>>2), r2 = r1 + 8;
            float b1v = g_bcf[which*128 + r1], b2v = g_bcf[which*128 + r2];
#pragma unroll
            for (int g = 0; g < 4; g++){
                int w = nw*32 + g*8 + 2*(l & 3);
                unsigned lp;
                unsigned hp = pack_hi(acc[f][g][0] + b1v, acc[f][g][1] + b1v, lp);
                *(unsigned*)&oh[base + (size_t)r1*128 + w] = hp;
                *(unsigned*)&ol[base + (size_t)r1*128 + w] = lp;
                hp = pack_hi(acc[f][g][2] + b2v, acc[f][g][3] + b2v, lp);
                *(unsigned*)&oh[base + (size_t)r2*128 + w] = hp;
                *(unsigned*)&ol[base + (size_t)r2*128 + w] = lp;
            }
        }
    }
}

// ============ attention: chunked staging, 96KB smem, 2 CTAs/SM ==============
// regions: A chunk 0..32K (hi/lo), B chunk 32K..64K (hi/lo), C (xp) 64K..96K.
// After GEMM1, S panels occupy 0..64K: Sh pn at pn*16K, Sl at 32K+pn*16K.
__global__ __launch_bounds__(256, 2) void attn_mma(void)
{
    extern __shared__ char dsm[];
    __shared__ float red[16];
    const int tid = threadIdx.x, l = tid & 31, wid = tid >> 5;
    const int mw = wid & 1, nw = wid >> 1;
    const int br = blockIdx.x, h = blockIdx.y, b = blockIdx.z;
    const uint32_t sb = smem_u32(dsm);
    const size_t slab = (size_t)(b*128 + h) * 32768;
    const char* aH = (const char*)(br ? g_x2h : g_x1h) + slab;
    const char* aL = (const char*)(br ? g_x2l : g_x1l) + slab;
    const char* bH = (const char*)(br ? g_xrh : g_xfh) + slab;
    const char* bL = (const char*)(br ? g_xrl : g_xfl) + slab;
    const char* pH = (const char*)g_xph + slab;
    const char* pL = (const char*)g_xpl + slab;

    auto stage1 = [&](int pn){
        for (int u = tid; u < 1024; u += 256){
            int c = u >> 3, j = u & 7;
            uint32_t d = SWZ((uint32_t)(c*128 + j*16));
            CP16(sb + 0     + d, aH + c*256 + pn*128 + j*16);
            CP16(sb + 16384 + d, aL + c*256 + pn*128 + j*16);
            CP16(sb + 32768 + d, bH + c*256 + pn*128 + j*16);
            CP16(sb + 49152 + d, bL + c*256 + pn*128 + j*16);
        }
    };
    auto stage_xp = [&](int pn){
        for (int u = tid; u < 1024; u += 256){
            int w = u >> 3, j = u & 7;
            uint32_t d = SWZ((uint32_t)(w*128 + j*16));
            CP16(sb + 65536 + d, pH + w*256 + pn*128 + j*16);
            CP16(sb + 81920 + d, pL + w*256 + pn*128 + j*16);
        }
    };

    float acc[4][4][4];
#pragma unroll
    for (int f=0;f<4;f++)
#pragma unroll
        for (int g=0;g<4;g++)
#pragma unroll
            for (int e=0;e<4;e++) acc[f][g][e] = 0.f;

    stage1(0); CP_COMMIT(); CP_WAIT0(); __syncthreads();
    gemm64(sb, 0, 16384, 32768, 49152, l, mw, nw, acc);
    __syncthreads();
    stage1(1);
    stage_xp(0);                  // prefetch xp chunk 0 into region C
    CP_COMMIT(); CP_WAIT0(); __syncthreads();
    gemm64(sb, 0, 16384, 32768, 49152, l, mw, nw, acc);

    float ls = 0.f, lq = 0.f;
#pragma unroll
    for (int f=0;f<4;f++)
#pragma unroll
        for (int g=0;g<4;g++)
#pragma unroll
            for (int e=0;e<4;e++){ ls += acc[f][g][e]; lq += acc[f][g][e]*acc[f][g][e]; }
    block_reduce_2(ls, lq, red);
    float mean = ls * (1.f/16384.f);
    float inv  = rsqrtf(lq * (1.f/16384.f) - mean*mean + EPSF);

    // write normalized S panels into 0..64K: Sh at pn*16K, Sl at 32K+pn*16K
#pragma unroll
    for (int f = 0; f < 4; f++){
        int c1 = mw*64 + f*16 + (l>>2), c2 = c1 + 8;
#pragma unroll
        for (int g = 0; g < 4; g++){
            int dd = nw*32 + g*8 + 2*(l & 3);
            uint32_t pn = (uint32_t)(dd >> 6)*16384;
            uint32_t byt = (uint32_t)((dd & 63)*2);
            unsigned lp;
            unsigned hp = pack_hi((acc[f][g][0]-mean)*inv, (acc[f][g][1]-mean)*inv, lp);
            *(unsigned*)(dsm + 0     + pn + SWZ((uint32_t)(c1*128) + byt)) = hp;
            *(unsigned*)(dsm + 32768 + pn + SWZ((uint32_t)(c1*128) + byt)) = lp;
            hp = pack_hi((acc[f][g][2]-mean)*inv, (acc[f][g][3]-mean)*inv, lp);
            *(unsigned*)(dsm + 0     + pn + SWZ((uint32_t)(c2*128) + byt)) = hp;
            *(unsigned*)(dsm + 32768 + pn + SWZ((uint32_t)(c2*128) + byt)) = lp;
        }
    }
    __syncthreads();

#pragma unroll
    for (int f=0;f<4;f++)
#pragma unroll
        for (int g=0;g<4;g++)
#pragma unroll
            for (int e=0;e<4;e++) acc[f][g][e] = 0.f;
    gemm64(sb, 0, 32768, 65536, 81920, l, mw, nw, acc);   // S chunk 0 x xp chunk 0
    __syncthreads();
    stage_xp(1); CP_COMMIT(); CP_WAIT0(); __syncthreads();
    gemm64(sb, 16384, 49152, 65536, 81920, l, mw, nw, acc); // S chunk 1 x xp chunk 1

    ls = 0.f; lq = 0.f;
#pragma unroll
    for (int f=0;f<4;f++)
#pragma unroll
        for (int g=0;g<4;g++)
#pragma unroll
            for (int e=0;e<4;e++){ ls += acc[f][g][e]; lq += acc[f][g][e]*acc[f][g][e]; }
    block_reduce_2(ls, lq, red);
    mean = ls * (1.f/16384.f);
    inv  = rsqrtf(lq * (1.f/16384.f) - mean*mean + EPSF);

    // epilogue: F -> fp16 channels-last directly into g_bhi via smem transpose
    unsigned short* tile = (unsigned short*)dsm;   // [w][c] 32KB, regions free now
#pragma unroll
    for (int f = 0; f < 4; f++){
        int c1 = mw*64 + f*16 + (l>>2), c2 = c1 + 8;
#pragma unroll
        for (int g = 0; g < 4; g++){
            int w = nw*32 + g*8 + 2*(l & 3);
            tile[(size_t)w*128 + c1]     = __half_as_ushort(__float2half((acc[f][g][0]-mean)*inv));
            tile[(size_t)(w+1)*128 + c1] = __half_as_ushort(__float2half((acc[f][g][1]-mean)*inv));
            tile[(size_t)w*128 + c2]     = __half_as_ushort(__float2half((acc[f][g][2]-mean)*inv));
            tile[(size_t)(w+1)*128 + c2] = __half_as_ushort(__float2half((acc[f][g][3]-mean)*inv));
        }
    }
    __syncthreads();
    const size_t rowb = (((size_t)b*130 + (h+1))*130 + 1)*384 + br*128;  // wp=1, ci base
    for (int u = tid; u < 2048; u += 256){
        int w = u >> 4, j = u & 15;
        uint4 v = *(uint4*)(dsm + w*256 + j*16);
        *(uint4*)((char*)g_bhi + (rowb + (size_t)w*384)*2 + j*16) = v;
    }
}

// ============ conv3x3 weight prep: fp16 [tap][chunk][o][ci] =================
__global__ void presplit_kernel(const float* __restrict__ Wm)
{
    int idx = blockIdx.x*256 + threadIdx.x;
    if (idx >= 9*6*384*64) return;
    int ci = idx & 63;
    int o  = (idx >> 6) % 384;
    int r  = idx >> 6; r /= 384;
    int chunk = r % 6, tap = r / 6;
    float v = Wm[(size_t)o*3456 + (chunk*64 + ci)*9 + tap];
    g_wh[idx] = __half_as_ushort(__float2half(v));
}

// ===== conv3x3 input (x third only) to channels-last fp16 ===================
__global__ __launch_bounds__(256) void padcvt_kernel(const float* __restrict__ x)
{
    __shared__ float tile[64*129];
    const int c0 = 256 + (blockIdx.x << 6), h = blockIdx.y, b = blockIdx.z;
    const int tid = threadIdx.x;
    for (int idx = tid; idx < 64*128; idx += 256){
        int ci = idx >> 7, w = idx & 127;
        tile[ci*129 + w] = x[((size_t)b*128 + (c0-256+ci))*HW + h*128 + w];
    }
    __syncthreads();
    const size_t obase = (((size_t)b*130 + (h+1))*130)*384;
    for (int idx = tid; idx < 128*8; idx += 256){
        int w = idx >> 3, u = idx & 7;
        unsigned Hp[4];
#pragma unroll
        for (int e2 = 0; e2 < 4; e2++){
            float v0 = tile[(u*8 + 2*e2    )*129 + w];
            float v1 = tile[(u*8 + 2*e2 + 1)*129 + w];
            Hp[e2] = pack_f16(v0, v1);
        }
        size_t off2 = (obase + (size_t)(w+1)*384 + c0 + u*8) * 2;
        *(uint4*)((char*)g_bhi + off2) = make_uint4(Hp[0],Hp[1],Hp[2],Hp[3]);
    }
}

// =================== conv3x3 via mma.sync fp16 single-pass ==================
#define OFF_AH 0
#define OFF_BH 16384
#define STAGE  33792

__global__ __launch_bounds__(256) void conv3x3_tc(
    const float* __restrict__ bm, const float* __restrict__ gamma,
    const float* __restrict__ beta, const float* __restrict__ rmean,
    const float* __restrict__ rvar, float* __restrict__ out)
{
    extern __shared__ char dsm[];
    const int tid = threadIdx.x, l = tid & 31, wid = tid >> 5;
    const int mw = wid & 1, nw = wid >> 1;
    const int h = blockIdx.y, o0 = blockIdx.x << 7, b = blockIdx.z;
    const uint32_t sb = smem_u32(dsm);

    float acc[4][4][4];
#pragma unroll
    for (int f=0;f<4;f++)
#pragma unroll
        for (int g=0;g<4;g++)
#pragma unroll
            for (int e=0;e<4;e++) acc[f][g][e] = 0.f;

    auto stage = [&](int it, int st){
        int tap = it/6, chunk = it - tap*6;
        int kh = tap/3;
        uint32_t s0 = sb + st*STAGE;
        const char* srcAh = (const char*)g_wh + (((size_t)tap*6 + chunk)*384 + o0)*128;
        for (int u = tid; u < 1024; u += 256){
            CP16(s0 + OFF_AH + SWZ(u*16), srcAh + u*16);
        }
        size_t rowbase = ((size_t)b*130 + (h+kh))*130*768 + (size_t)chunk*128;
        const char* BH = (const char*)g_bhi;
        for (int u = tid; u < 1040; u += 256){
            int wp = u >> 3, j = u & 7;
            CP16(s0 + OFF_BH + SWZ(wp*128 + j*16), BH + rowbase + (size_t)wp*768 + j*16);
        }
    };

    stage(0, 0); CP_COMMIT(); CP_WAIT0(); __syncthreads();

    for (int it = 0; it < 54; it++){
        const int p = it & 1;
        if (it + 1 < 54){ stage(it+1, 1-p); CP_COMMIT(); }

        const int kw = (it/6) % 3;
        const uint32_t s0 = sb + p*STAGE;
#pragma unroll
        for (int ks = 0; ks < 4; ks++){
            uint32_t ah[4][4], bh[4][2];
            const uint32_t abyte = ks*32 + ((l>>4)<<4);
#pragma unroll
            for (int f = 0; f < 4; f++){
                int row = mw*64 + f*16 + (l & 15);
                uint32_t off = SWZ((uint32_t)(row*128) + abyte);
                LDSM4(ah[f][0],ah[f][1],ah[f][2],ah[f][3], s0 + OFF_AH + off);
            }
            const uint32_t bbyte = ks*32 + (((l>>3)&1)<<4);
#pragma unroll
            for (int g2 = 0; g2 < 2; g2++){
                int rowb = nw*32 + g2*16 + kw + (l & 7) + ((l>>4)<<3);
                uint32_t off = SWZ((uint32_t)(rowb*128) + bbyte);
                uint32_t t0,t1,t2,t3;
                LDSM4(t0,t1,t2,t3, s0 + OFF_BH + off);
                bh[g2*2][0]=t0; bh[g2*2][1]=t1; bh[g2*2+1][0]=t2; bh[g2*2+1][1]=t3;
            }
#pragma unroll
            for (int f = 0; f < 4; f++)
#pragma unroll
                for (int g = 0; g < 4; g++){
                    MMAF16(acc[f][g], ah[f], bh[g]);
                }
        }
        CP_WAIT0();
        __syncthreads();
    }

#pragma unroll
    for (int f = 0; f < 4; f++){
        int o1 = o0 + mw*64 + f*16 + (l >> 2);
        int o2 = o1 + 8;
        float sc1 = gamma[o1] * rsqrtf(rvar[o1] + EPSF);
        float sh1 = beta[o1] + (bm[o1] - rmean[o1]) * sc1;
        float sc2 = gamma[o2] * rsqrtf(rvar[o2] + EPSF);
        float sh2 = beta[o2] + (bm[o2] - rmean[o2]) * sc2;
        float* r1 = out + ((size_t)(b*384 + o1))*HW + (size_t)h*128;
        float* r2 = out + ((size_t)(b*384 + o2))*HW + (size_t)h*128;
#pragma unroll
        for (int g = 0; g < 4; g++){
            int w = nw*32 + g*8 + 2*(l & 3);
            float2 v1, v2;
            v1.x = fmaxf(fmaf(acc[f][g][0], sc1, sh1), 0.f);
            v1.y = fmaxf(fmaf(acc[f][g][1], sc1, sh1), 0.f);
            v2.x = fmaxf(fmaf(acc[f][g][2], sc2, sh2), 0.f);
            v2.y = fmaxf(fmaf(acc[f][g][3], sc2, sh2), 0.f);
            *(float2*)(r1 + w) = v1;
            *(float2*)(r2 + w) = v2;
        }
    }
}

// =============================================================================
extern "C" void kernel_launch(void* const* d_in, const int* in_sizes, int n_in,
                              void* d_out, int out_size)
{
    const float* x  = (const float*)d_in[0];
    const float* xf = (const float*)d_in[1];
    const float* xr = (const float*)d_in[2];
    const float* Wx = (const float*)d_in[3];
    const float* bx = (const float*)d_in[4];
    const float* W1 = (const float*)d_in[5];
    const float* b1 = (const float*)d_in[6];
    const float* W2 = (const float*)d_in[7];
    const float* b2 = (const float*)d_in[8];
    const float* Wf = (const float*)d_in[9];
    const float* bf = (const float*)d_in[10];
    const float* Wr = (const float*)d_in[11];
    const float* br_ = (const float*)d_in[12];
    const float* Wm = (const float*)d_in[13];
    const float* bm = (const float*)d_in[14];
    const float* gamma = (const float*)d_in[15];
    const float* beta  = (const float*)d_in[16];
    const float* rmean = (const float*)d_in[17];
    const float* rvar  = (const float*)d_in[18];
    float* out = (float*)d_out;

    cudaFuncSetAttribute(xpose_cvt,   cudaFuncAttributeMaxDynamicSharedMemorySize, 68096);
    cudaFuncSetAttribute(wcompose_kernel, cudaFuncAttributeMaxDynamicSharedMemorySize, 65536);
    cudaFuncSetAttribute(conv1x1_mma, cudaFuncAttributeMaxDynamicSharedMemorySize, 65536);
    cudaFuncSetAttribute(attn_mma,    cudaFuncAttributeMaxDynamicSharedMemorySize, 98304);
    cudaFuncSetAttribute(conv3x3_tc,  cudaFuncAttributeMaxDynamicSharedMemorySize, 2*STAGE);

    xpose_cvt<<<dim3(3, 128, 8), 256, 68096>>>(x, xf, xr);
    wcompose_kernel<<<5, 256, 65536>>>(Wx, bx, W1, b1, W2, b2, Wf, bf, Wr, br_);
    wsplit_kernel<<<320, 256>>>();
    conv1x1_mma<<<dim3(5, 128, 8), 256, 65536>>>();
    attn_mma<<<dim3(2, 128, 8), 256, 98304>>>();
    presplit_kernel<<<5184, 256>>>(Wm);
    padcvt_kernel<<<dim3(2, 128, 8), 256>>>(x);
    conv3x3_tc<<<dim3(3, 128, 8), 256, 2*STAGE>>>(bm, gamma, beta, rmean, rvar, out);
}

// round 9
// speedup vs baseline: 8.4587x; 1.1687x over previous
#include <cuda_runtime.h>
#include <cuda_bf16.h>
#include <cuda_fp16.h>
#include <cstdint>

#define EPSF 1e-5f
#define HW   16384
#define CHW  2097152

// ---------------- scratch (static device memory) ----------------
__device__ float g_wcf[5*16384];                        // composed 1x1 weights fp32
__device__ float g_bcf[5*128];                          // composed biases
__device__ __align__(16) unsigned short g_wsh[5*2*128*64];   // fp16 [which][pn][o][ci64]
__device__ __align__(16) unsigned short g_tih[3ull*8*CHW];   // fp16 inputs T: [inp][b][h][w][c]
__device__ __align__(16) unsigned short g_x1h[8*CHW];        // fp16 [b][h][c][w]
__device__ __align__(16) unsigned short g_x2h[8*CHW];
__device__ __align__(16) unsigned short g_xfh[8*CHW];
__device__ __align__(16) unsigned short g_xrh[8*CHW];
__device__ __align__(16) unsigned short g_xph[8*CHW];        // fp16 [b][h][w][d]
__device__ unsigned short g_wh[9*6*384*64];             // conv3x3 W fp16: [tap][chunk][o][ci]
__device__ unsigned short g_bhi[8ull*130*130*384];      // conv3x3 in fp16: [b][hp][wp][ci]

// ---------------- helpers ----------------
__device__ __forceinline__ uint32_t smem_u32(const void* p){
    uint32_t a; asm("{ .reg .u64 t; cvta.to.shared.u64 t, %1; cvt.u32.u64 %0, t; }"
                    : "=r"(a) : "l"(p)); return a;
}
#define SWZ(x) ((x) ^ (((x)>>3)&0x70))
#define CP16(dst, src) asm volatile("cp.async.cg.shared.global [%0], [%1], 16;" \
    :: "r"((uint32_t)(dst)), "l"((const void*)(src)) : "memory")
#define CP_COMMIT() asm volatile("cp.async.commit_group;" ::: "memory")
#define CP_WAIT0()  asm volatile("cp.async.wait_group 0;" ::: "memory")
#define CP_WAIT1()  asm volatile("cp.async.wait_group 1;" ::: "memory")
#define LDSM4(r0,r1,r2,r3,a) asm volatile( \
    "ldmatrix.sync.aligned.m8n8.x4.shared.b16 {%0,%1,%2,%3}, [%4];" \
    : "=r"(r0),"=r"(r1),"=r"(r2),"=r"(r3) : "r"(a))
#define MMAF16(c,a,b) asm volatile( \
    "mma.sync.aligned.m16n8k16.row.col.f32.f16.f16.f32 " \
    "{%0,%1,%2,%3},{%4,%5,%6,%7},{%8,%9},{%0,%1,%2,%3};" \
    : "+f"((c)[0]),"+f"((c)[1]),"+f"((c)[2]),"+f"((c)[3]) \
    : "r"((a)[0]),"r"((a)[1]),"r"((a)[2]),"r"((a)[3]), "r"((b)[0]),"r"((b)[1]))

__device__ __forceinline__ unsigned pack_f16(float v0, float v1){
    unsigned hp; asm("cvt.rn.f16x2.f32 %0, %1, %2;" : "=r"(hp) : "f"(v1), "f"(v0));
    return hp;
}

// 128x128x64 GEMM chunk, single-pass fp16. a0/b0 = byte offsets of panels in smem.
__device__ __forceinline__ void gemm64f(uint32_t sb, uint32_t a0, uint32_t b0,
                                        int l, int mw, int nw, float acc[4][4][4])
{
#pragma unroll
    for (int ks = 0; ks < 4; ks++){
        uint32_t ah[4][4], bh[4][2];
        const uint32_t abyte = ks*32 + ((l>>4)<<4);
#pragma unroll
        for (int f = 0; f < 4; f++){
            int row = mw*64 + f*16 + (l & 15);
            uint32_t off = SWZ((uint32_t)(row*128) + abyte);
            LDSM4(ah[f][0],ah[f][1],ah[f][2],ah[f][3], sb + a0 + off);
        }
        const uint32_t bbyte = ks*32 + (((l>>3)&1)<<4);
#pragma unroll
        for (int g2 = 0; g2 < 2; g2++){
            int rowb = nw*32 + g2*16 + (l & 7) + ((l>>4)<<3);
            uint32_t off = SWZ((uint32_t)(rowb*128) + bbyte);
            uint32_t t0,t1,t2,t3;
            LDSM4(t0,t1,t2,t3, sb + b0 + off);
            bh[g2*2][0]=t0; bh[g2*2][1]=t1; bh[g2*2+1][0]=t2; bh[g2*2+1][1]=t3;
        }
#pragma unroll
        for (int f = 0; f < 4; f++)
#pragma unroll
            for (int g = 0; g < 4; g++)
                MMAF16(acc[f][g], ah[f], bh[g]);
    }
}

__device__ __forceinline__ void block_reduce_2(float& s, float& q, float* red)
{
#pragma unroll
    for (int off=16; off>0; off>>=1){
        s += __shfl_down_sync(0xffffffffu, s, off);
        q += __shfl_down_sync(0xffffffffu, q, off);
    }
    const int wid = threadIdx.x >> 5;
    if ((threadIdx.x & 31) == 0){ red[wid] = s; red[8+wid] = q; }
    __syncthreads();
    s = 0.f; q = 0.f;
#pragma unroll
    for (int i=0;i<8;i++){ s += red[i]; q += red[8+i]; }
    __syncthreads();
}

// ============ transpose+convert inputs: [b][c][h][w] -> [inp][b][h][w][c] fp16 =====
__global__ __launch_bounds__(256) void xpose_cvt(const float* __restrict__ x,
    const float* __restrict__ xf, const float* __restrict__ xr)
{
    extern __shared__ float tl[];   // [128][133]
    const int inp = blockIdx.x, h = blockIdx.y, b = blockIdx.z;
    const float* src = inp==0 ? x : (inp==1 ? xf : xr);
    const int tid = threadIdx.x;
    const float* sp = src + (size_t)b*CHW + (size_t)h*128;
    for (int u = tid; u < 4096; u += 256){
        int c = u >> 5, q = u & 31;
        float4 v = *(const float4*)(sp + (size_t)c*HW + 4*q);
        float* d = tl + c*133 + 4*q;
        d[0]=v.x; d[1]=v.y; d[2]=v.z; d[3]=v.w;
    }
    __syncthreads();
    const size_t obase = ((size_t)inp*1024 + b*128 + h) * 16384;
    for (int u = tid; u < 4096; u += 256){
        int cg = u & 31, w = u >> 5;
        float v0 = tl[(4*cg+0)*133 + w], v1 = tl[(4*cg+1)*133 + w];
        float v2 = tl[(4*cg+2)*133 + w], v3 = tl[(4*cg+3)*133 + w];
        unsigned hp0 = pack_f16(v0, v1);
        unsigned hp1 = pack_f16(v2, v3);
        *(uint2*)&g_tih[obase + (size_t)w*128 + 4*cg] = make_uint2(hp0, hp1);
    }
}

// ============ compose 1x1 weights: which 0:Wx 1:W1@Wx 2:W2@Wx 3:Wf 4:Wr =====
__global__ __launch_bounds__(256) void wcompose_kernel(
    const float* __restrict__ Wx, const float* __restrict__ bx,
    const float* __restrict__ W1, const float* __restrict__ b1,
    const float* __restrict__ W2, const float* __restrict__ b2,
    const float* __restrict__ Wf, const float* __restrict__ bf,
    const float* __restrict__ Wr, const float* __restrict__ br_)
{
    extern __shared__ float S[];
    const int which = blockIdx.x, tid = threadIdx.x;
    if (which == 0 || which >= 3){
        const float* Ws = which==0 ? Wx : (which==3 ? Wf : Wr);
        const float* bs = which==0 ? bx : (which==3 ? bf : br_);
        for (int i = tid; i < 16384; i += 256) g_wcf[which*16384 + i] = Ws[i];
        if (tid < 128) g_bcf[which*128 + tid] = bs[tid];
        return;
    }
    const float* Wo = (which==1) ? W1 : W2;
    const float* bo = (which==1) ? b1 : b2;
    for (int i = tid; i < 16384; i += 256) S[i] = Wx[i];
    __syncthreads();
    int r = tid >> 1, c0 = (tid & 1) * 64;
    float acc[64];
#pragma unroll
    for (int j = 0; j < 64; j++) acc[j] = 0.f;
    for (int k = 0; k < 128; k++){
        float a = Wo[r*128 + k];
#pragma unroll
        for (int j = 0; j < 64; j++) acc[j] = fmaf(a, S[k*128 + c0 + j], acc[j]);
    }
    for (int j = 0; j < 64; j++) g_wcf[which*16384 + r*128 + c0 + j] = acc[j];
    if (tid < 128){
        float s = bo[tid];
        for (int k = 0; k < 128; k++) s = fmaf(Wo[tid*128 + k], bx[k], s);
        g_bcf[which*128 + tid] = s;
    }
}

// split composed weights to fp16 panels [which][pn][o][ci64]
__global__ void wsplit_kernel()
{
    int idx = blockIdx.x*256 + threadIdx.x;
    if (idx >= 81920) return;
    int ci = idx & 63, o = (idx >> 6) & 127, pn = (idx >> 13) & 1, which = idx >> 14;
    g_wsh[idx] = __half_as_ushort(__float2half(g_wcf[which*16384 + o*128 + pn*64 + ci]));
}

// ============ conv1x1: single-pass fp16, 64KB smem, double-buffered =========
__global__ __launch_bounds__(256, 2) void conv1x1_mma(void)
{
    extern __shared__ char dsm[];
    const int tid = threadIdx.x, l = tid & 31, wid = tid >> 5;
    const int mw = wid & 1, nw = wid >> 1;
    const int which = blockIdx.x, h = blockIdx.y, b = blockIdx.z;
    const uint32_t sb = smem_u32(dsm);
    const int inp = (which < 3) ? 0 : which - 2;

    const char* wH = (const char*)g_wsh + which*32768;
    const size_t slab = ((size_t)inp*1024 + b*128 + h)*32768;
    const char* tH = (const char*)g_tih + slab;

    auto stage = [&](int pn){
        uint32_t base = pn*32768;
        for (int u = tid; u < 1024; u += 256){
            CP16(sb + base + SWZ((uint32_t)(u*16)), wH + pn*16384 + u*16);
            int w = u >> 3, j = u & 7;
            CP16(sb + base + 16384 + SWZ((uint32_t)(w*128 + j*16)), tH + w*256 + pn*128 + j*16);
        }
    };

    float acc[4][4][4];
#pragma unroll
    for (int f=0;f<4;f++)
#pragma unroll
        for (int g=0;g<4;g++)
#pragma unroll
            for (int e=0;e<4;e++) acc[f][g][e] = 0.f;

    stage(0); CP_COMMIT();
    stage(1); CP_COMMIT();
    CP_WAIT1(); __syncthreads();
    gemm64f(sb, 0, 16384, l, mw, nw, acc);
    CP_WAIT0(); __syncthreads();
    gemm64f(sb, 32768, 49152, l, mw, nw, acc);

    const size_t base = (size_t)(b*128 + h)*16384;
    if (which == 0){
        // xp layout [w][d]: transpose through smem, then uint4 row copies
        __syncthreads();
        unsigned short* tile = (unsigned short*)dsm;
#pragma unroll
        for (int f = 0; f < 4; f++){
            int r1 = mw*64 + f*16 + (l>>2), r2 = r1 + 8;
            float b1v = g_bcf[r1], b2v = g_bcf[r2];
#pragma unroll
            for (int g = 0; g < 4; g++){
                int w = nw*32 + g*8 + 2*(l & 3);
                tile[(size_t)w*128 + r1]     = __half_as_ushort(__float2half(acc[f][g][0] + b1v));
                tile[(size_t)(w+1)*128 + r1] = __half_as_ushort(__float2half(acc[f][g][1] + b1v));
                tile[(size_t)w*128 + r2]     = __half_as_ushort(__float2half(acc[f][g][2] + b2v));
                tile[(size_t)(w+1)*128 + r2] = __half_as_ushort(__float2half(acc[f][g][3] + b2v));
            }
        }
        __syncthreads();
        for (int u = tid; u < 2048; u += 256){
            *(uint4*)((char*)(g_xph + base) + u*16) = *(uint4*)(dsm + u*16);
        }
    } else {
        unsigned short* oh;
        if (which == 1) oh = g_x1h;
        else if (which == 2) oh = g_x2h;
        else if (which == 3) oh = g_xfh;
        else oh = g_xrh;
#pragma unroll
        for (int f = 0; f < 4; f++){
            int r1 = mw*64 + f*16 + (l>>2), r2 = r1 + 8;
            float b1v = g_bcf[which*128 + r1], b2v = g_bcf[which*128 + r2];
#pragma unroll
            for (int g = 0; g < 4; g++){
                int w = nw*32 + g*8 + 2*(l & 3);
                *(unsigned*)&oh[base + (size_t)r1*128 + w] = pack_f16(acc[f][g][0] + b1v, acc[f][g][1] + b1v);
                *(unsigned*)&oh[base + (size_t)r2*128 + w] = pack_f16(acc[f][g][2] + b2v, acc[f][g][3] + b2v);
            }
        }
    }
}

// ============ attention: single-pass fp16, 64KB smem ========================
// regions: A 0..32K (pn panels), B 32..64K (pn panels). S overwrites A; xp overwrites B.
__global__ __launch_bounds__(256, 2) void attn_mma(void)
{
    extern __shared__ char dsm[];
    __shared__ float red[16];
    const int tid = threadIdx.x, l = tid & 31, wid = tid >> 5;
    const int mw = wid & 1, nw = wid >> 1;
    const int br = blockIdx.x, h = blockIdx.y, b = blockIdx.z;
    const uint32_t sb = smem_u32(dsm);
    const size_t slab = (size_t)(b*128 + h) * 32768;
    const char* aH = (const char*)(br ? g_x2h : g_x1h) + slab;
    const char* bH = (const char*)(br ? g_xrh : g_xfh) + slab;
    const char* pH = (const char*)g_xph + slab;

    for (int u = tid; u < 2048; u += 256){
        int c = u >> 4, j = u & 15;
        int pn = j >> 3, jj = j & 7;
        uint32_t d = pn*16384 + SWZ((uint32_t)(c*128 + jj*16));
        CP16(sb + d,         aH + c*256 + pn*128 + jj*16);
        CP16(sb + 32768 + d, bH + c*256 + pn*128 + jj*16);
    }
    CP_COMMIT(); CP_WAIT0(); __syncthreads();

    float acc[4][4][4];
#pragma unroll
    for (int f=0;f<4;f++)
#pragma unroll
        for (int g=0;g<4;g++)
#pragma unroll
            for (int e=0;e<4;e++) acc[f][g][e] = 0.f;
    gemm64f(sb, 0,     32768, l, mw, nw, acc);
    gemm64f(sb, 16384, 49152, l, mw, nw, acc);

    float ls = 0.f, lq = 0.f;
#pragma unroll
    for (int f=0;f<4;f++)
#pragma unroll
        for (int g=0;g<4;g++)
#pragma unroll
            for (int e=0;e<4;e++){ ls += acc[f][g][e]; lq += acc[f][g][e]*acc[f][g][e]; }
    block_reduce_2(ls, lq, red);
    float mean = ls * (1.f/16384.f);
    float inv  = rsqrtf(lq * (1.f/16384.f) - mean*mean + EPSF);

    // stage xp into B region (gemm1 done reading it — reduce's barriers cover)
    for (int u = tid; u < 2048; u += 256){
        int w = u >> 4, j = u & 15;
        int pn = j >> 3, jj = j & 7;
        CP16(sb + 32768 + pn*16384 + SWZ((uint32_t)(w*128 + jj*16)),
             pH + w*256 + pn*128 + jj*16);
    }
    CP_COMMIT();

    // write normalized S (fp16) into A region panels [pn][c][d64]
#pragma unroll
    for (int f = 0; f < 4; f++){
        int c1 = mw*64 + f*16 + (l>>2), c2 = c1 + 8;
#pragma unroll
        for (int g = 0; g < 4; g++){
            int dd = nw*32 + g*8 + 2*(l & 3);
            uint32_t pn = (uint32_t)(dd >> 6)*16384;
            uint32_t byt = (uint32_t)((dd & 63)*2);
            *(unsigned*)(dsm + pn + SWZ((uint32_t)(c1*128) + byt)) =
                pack_f16((acc[f][g][0]-mean)*inv, (acc[f][g][1]-mean)*inv);
            *(unsigned*)(dsm + pn + SWZ((uint32_t)(c2*128) + byt)) =
                pack_f16((acc[f][g][2]-mean)*inv, (acc[f][g][3]-mean)*inv);
        }
    }
    CP_WAIT0(); __syncthreads();

#pragma unroll
    for (int f=0;f<4;f++)
#pragma unroll
        for (int g=0;g<4;g++)
#pragma unroll
            for (int e=0;e<4;e++) acc[f][g][e] = 0.f;
    gemm64f(sb, 0,     32768, l, mw, nw, acc);
    gemm64f(sb, 16384, 49152, l, mw, nw, acc);

    ls = 0.f; lq = 0.f;
#pragma unroll
    for (int f=0;f<4;f++)
#pragma unroll
        for (int g=0;g<4;g++)
#pragma unroll
            for (int e=0;e<4;e++){ ls += acc[f][g][e]; lq += acc[f][g][e]*acc[f][g][e]; }
    block_reduce_2(ls, lq, red);
    mean = ls * (1.f/16384.f);
    inv  = rsqrtf(lq * (1.f/16384.f) - mean*mean + EPSF);

    // epilogue: F -> fp16 channels-last into g_bhi via smem transpose
    unsigned short* tile = (unsigned short*)dsm;
#pragma unroll
    for (int f = 0; f < 4; f++){
        int c1 = mw*64 + f*16 + (l>>2), c2 = c1 + 8;
#pragma unroll
        for (int g = 0; g < 4; g++){
            int w = nw*32 + g*8 + 2*(l & 3);
            tile[(size_t)w*128 + c1]     = __half_as_ushort(__float2half((acc[f][g][0]-mean)*inv));
            tile[(size_t)(w+1)*128 + c1] = __half_as_ushort(__float2half((acc[f][g][1]-mean)*inv));
            tile[(size_t)w*128 + c2]     = __half_as_ushort(__float2half((acc[f][g][2]-mean)*inv));
            tile[(size_t)(w+1)*128 + c2] = __half_as_ushort(__float2half((acc[f][g][3]-mean)*inv));
        }
    }
    __syncthreads();
    const size_t rowb = (((size_t)b*130 + (h+1))*130 + 1)*384 + br*128;
    for (int u = tid; u < 2048; u += 256){
        int w = u >> 4, j = u & 15;
        uint4 v = *(uint4*)(dsm + w*256 + j*16);
        *(uint4*)((char*)g_bhi + (rowb + (size_t)w*384)*2 + j*16) = v;
    }
}

// ============ conv3x3 weight prep: fp16 [tap][chunk][o][ci] =================
__global__ void presplit_kernel(const float* __restrict__ Wm)
{
    int idx = blockIdx.x*256 + threadIdx.x;
    if (idx >= 9*6*384*64) return;
    int ci = idx & 63;
    int o  = (idx >> 6) % 384;
    int r  = idx >> 6; r /= 384;
    int chunk = r % 6, tap = r / 6;
    float v = Wm[(size_t)o*3456 + (chunk*64 + ci)*9 + tap];
    g_wh[idx] = __half_as_ushort(__float2half(v));
}

// ===== conv3x3 input (x third only) to channels-last fp16 ===================
__global__ __launch_bounds__(256) void padcvt_kernel(const float* __restrict__ x)
{
    __shared__ float tile[64*129];
    const int c0 = 256 + (blockIdx.x << 6), h = blockIdx.y, b = blockIdx.z;
    const int tid = threadIdx.x;
    for (int idx = tid; idx < 64*128; idx += 256){
        int ci = idx >> 7, w = idx & 127;
        tile[ci*129 + w] = x[((size_t)b*128 + (c0-256+ci))*HW + h*128 + w];
    }
    __syncthreads();
    const size_t obase = (((size_t)b*130 + (h+1))*130)*384;
    for (int idx = tid; idx < 128*8; idx += 256){
        int w = idx >> 3, u = idx & 7;
        unsigned Hp[4];
#pragma unroll
        for (int e2 = 0; e2 < 4; e2++){
            float v0 = tile[(u*8 + 2*e2    )*129 + w];
            float v1 = tile[(u*8 + 2*e2 + 1)*129 + w];
            Hp[e2] = pack_f16(v0, v1);
        }
        size_t off2 = (obase + (size_t)(w+1)*384 + c0 + u*8) * 2;
        *(uint4*)((char*)g_bhi + off2) = make_uint4(Hp[0],Hp[1],Hp[2],Hp[3]);
    }
}

// =================== conv3x3 via mma.sync fp16 single-pass ==================
#define OFF_AH 0
#define OFF_BH 16384
#define STAGE  33792

__global__ __launch_bounds__(256, 2) void conv3x3_tc(
    const float* __restrict__ bm, const float* __restrict__ gamma,
    const float* __restrict__ beta, const float* __restrict__ rmean,
    const float* __restrict__ rvar, float* __restrict__ out)
{
    extern __shared__ char dsm[];
    const int tid = threadIdx.x, l = tid & 31, wid = tid >> 5;
    const int mw = wid & 1, nw = wid >> 1;
    const int h = blockIdx.y, o0 = blockIdx.x << 7, b = blockIdx.z;
    const uint32_t sb = smem_u32(dsm);

    float acc[4][4][4];
#pragma unroll
    for (int f=0;f<4;f++)
#pragma unroll
        for (int g=0;g<4;g++)
#pragma unroll
            for (int e=0;e<4;e++) acc[f][g][e] = 0.f;

    auto stage = [&](int it, int st){
        int tap = it/6, chunk = it - tap*6;
        int kh = tap/3;
        uint32_t s0 = sb + st*STAGE;
        const char* srcAh = (const char*)g_wh + (((size_t)tap*6 + chunk)*384 + o0)*128;
        for (int u = tid; u < 1024; u += 256){
            CP16(s0 + OFF_AH + SWZ(u*16), srcAh + u*16);
        }
        size_t rowbase = ((size_t)b*130 + (h+kh))*130*768 + (size_t)chunk*128;
        const char* BH = (const char*)g_bhi;
        for (int u = tid; u < 1040; u += 256){
            int wp = u >> 3, j = u & 7;
            CP16(s0 + OFF_BH + SWZ(wp*128 + j*16), BH + rowbase + (size_t)wp*768 + j*16);
        }
    };

    stage(0, 0); CP_COMMIT(); CP_WAIT0(); __syncthreads();

    for (int it = 0; it < 54; it++){
        const int p = it & 1;
        if (it + 1 < 54){ stage(it+1, 1-p); CP_COMMIT(); }

        const int kw = (it/6) % 3;
        const uint32_t s0 = sb + p*STAGE;
#pragma unroll
        for (int ks = 0; ks < 4; ks++){
            uint32_t ah[4][4], bh[4][2];
            const uint32_t abyte = ks*32 + ((l>>4)<<4);
#pragma unroll
            for (int f = 0; f < 4; f++){
                int row = mw*64 + f*16 + (l & 15);
                uint32_t off = SWZ((uint32_t)(row*128) + abyte);
                LDSM4(ah[f][0],ah[f][1],ah[f][2],ah[f][3], s0 + OFF_AH + off);
            }
            const uint32_t bbyte = ks*32 + (((l>>3)&1)<<4);
#pragma unroll
            for (int g2 = 0; g2 < 2; g2++){
                int rowb = nw*32 + g2*16 + kw + (l & 7) + ((l>>4)<<3);
                uint32_t off = SWZ((uint32_t)(rowb*128) + bbyte);
                uint32_t t0,t1,t2,t3;
                LDSM4(t0,t1,t2,t3, s0 + OFF_BH + off);
                bh[g2*2][0]=t0; bh[g2*2][1]=t1; bh[g2*2+1][0]=t2; bh[g2*2+1][1]=t3;
            }
#pragma unroll
            for (int f = 0; f < 4; f++)
#pragma unroll
                for (int g = 0; g < 4; g++)
                    MMAF16(acc[f][g], ah[f], bh[g]);
        }
        CP_WAIT0();
        __syncthreads();
    }

#pragma unroll
    for (int f = 0; f < 4; f++){
        int o1 = o0 + mw*64 + f*16 + (l >> 2);
        int o2 = o1 + 8;
        float sc1 = gamma[o1] * rsqrtf(rvar[o1] + EPSF);
        float sh1 = beta[o1] + (bm[o1] - rmean[o1]) * sc1;
        float sc2 = gamma[o2] * rsqrtf(rvar[o2] + EPSF);
        float sh2 = beta[o2] + (bm[o2] - rmean[o2]) * sc2;
        float* r1 = out + ((size_t)(b*384 + o1))*HW + (size_t)h*128;
        float* r2 = out + ((size_t)(b*384 + o2))*HW + (size_t)h*128;
#pragma unroll
        for (int g = 0; g < 4; g++){
            int w = nw*32 + g*8 + 2*(l & 3);
            float2 v1, v2;
            v1.x = fmaxf(fmaf(acc[f][g][0], sc1, sh1), 0.f);
            v1.y = fmaxf(fmaf(acc[f][g][1], sc1, sh1), 0.f);
            v2.x = fmaxf(fmaf(acc[f][g][2], sc2, sh2), 0.f);
            v2.y = fmaxf(fmaf(acc[f][g][3], sc2, sh2), 0.f);
            *(float2*)(r1 + w) = v1;
            *(float2*)(r2 + w) = v2;
        }
    }
}

// =============================================================================
extern "C" void kernel_launch(void* const* d_in, const int* in_sizes, int n_in,
                              void* d_out, int out_size)
{
    const float* x  = (const float*)d_in[0];
    const float* xf = (const float*)d_in[1];
    const float* xr = (const float*)d_in[2];
    const float* Wx = (const float*)d_in[3];
    const float* bx = (const float*)d_in[4];
    const float* W1 = (const float*)d_in[5];
    const float* b1 = (const float*)d_in[6];
    const float* W2 = (const float*)d_in[7];
    const float* b2 = (const float*)d_in[8];
    const float* Wf = (const float*)d_in[9];
    const float* bf = (const float*)d_in[10];
    const float* Wr = (const float*)d_in[11];
    const float* br_ = (const float*)d_in[12];
    const float* Wm = (const float*)d_in[13];
    const float* bm = (const float*)d_in[14];
    const float* gamma = (const float*)d_in[15];
    const float* beta  = (const float*)d_in[16];
    const float* rmean = (const float*)d_in[17];
    const float* rvar  = (const float*)d_in[18];
    float* out = (float*)d_out;

    cudaFuncSetAttribute(xpose_cvt,   cudaFuncAttributeMaxDynamicSharedMemorySize, 68096);
    cudaFuncSetAttribute(wcompose_kernel, cudaFuncAttributeMaxDynamicSharedMemorySize, 65536);
    cudaFuncSetAttribute(conv1x1_mma, cudaFuncAttributeMaxDynamicSharedMemorySize, 65536);
    cudaFuncSetAttribute(attn_mma,    cudaFuncAttributeMaxDynamicSharedMemorySize, 65536);
    cudaFuncSetAttribute(conv3x3_tc,  cudaFuncAttributeMaxDynamicSharedMemorySize, 2*STAGE);

    xpose_cvt<<<dim3(3, 128, 8), 256, 68096>>>(x, xf, xr);
    wcompose_kernel<<<5, 256, 65536>>>(Wx, bx, W1, b1, W2, b2, Wf, bf, Wr, br_);
    wsplit_kernel<<<320, 256>>>();
    conv1x1_mma<<<dim3(5, 128, 8), 256, 65536>>>();
    attn_mma<<<dim3(2, 128, 8), 256, 65536>>>();
    presplit_kernel<<<5184, 256>>>(Wm);
    padcvt_kernel<<<dim3(2, 128, 8), 256>>>(x);
    conv3x3_tc<<<dim3(3, 128, 8), 256, 2*STAGE>>>(bm, gamma, beta, rmean, rvar, out);
}